// round 2
// baseline (speedup 1.0000x reference)
#include <cuda_runtime.h>
#include <cuda_bf16.h>
#include <math.h>

// ---------------- problem constants ----------------
#define BB    8
#define SS    512
#define DD    2048
#define HH    16
#define DOWN  512
#define UP    2048
#define RR    512
#define VHD   128          // UP/H
#define MROWS (BB*SS)      // 4096
#define ZB    (BB*HH)      // 128 batched heads
#define QKDIM (VHD+RR)     // 640
#define INV_SCALE 0.0294627825494394758f   // 1/(sqrt(128)+sqrt(512))

// ---------------- scratch (device globals; no allocs allowed) ----------------
__device__ float g_cq  [(size_t)MROWS*DOWN];
__device__ float g_ckv [(size_t)MROWS*DOWN];
__device__ float g_qc  [(size_t)MROWS*UP];
__device__ float g_kc  [(size_t)MROWS*UP];
__device__ float g_vc  [(size_t)MROWS*UP];
__device__ float g_qr  [(size_t)MROWS*RR*HH];
__device__ float g_kr  [(size_t)MROWS*RR];
__device__ float g_krr [(size_t)MROWS*RR];
__device__ float g_qf  [(size_t)ZB*SS*QKDIM];
__device__ float g_kf  [(size_t)ZB*SS*QKDIM];
__device__ float g_sc  [(size_t)ZB*SS*SS];
__device__ float g_of  [(size_t)MROWS*UP];
__device__ float g_sin [SS*(RR/2)];
__device__ float g_cos [SS*(RR/2)];

// ---------------- generic 128x128x8 fp32 GEMM tile ----------------
// TB=false: C = A[M,K](lda) * B[K,N](ldb)    (row-major both)
// TB=true : C = A[M,K](lda) * B[N,K](ldb)^T
template<bool TB>
__device__ __forceinline__ void gemm_tile(
    const float* __restrict__ A, int lda,
    const float* __restrict__ B, int ldb,
    const float* __restrict__ bias, float scale,
    float* __restrict__ C, int ldc, int K,
    int brow, int bcol)
{
    __shared__ float As[8][128];
    __shared__ float Bs[8][128];
    const int tid = threadIdx.x;

    const float* Ab = A + (size_t)brow * 128 * lda;

    const int a_row  = tid >> 1;         // 0..127
    const int a_col  = (tid & 1) * 4;    // 0 or 4
    const int bn_row = tid >> 5;         // 0..7   (k)
    const int bn_col = (tid & 31) * 4;   // 0..124 (n)
    const int bt_row = tid >> 1;         // 0..127 (n)
    const int bt_col = (tid & 1) * 4;    // 0 or 4 (k)

    const int trow = (tid >> 4) * 8;
    const int tcol = (tid & 15) * 8;

    float acc[8][8];
    #pragma unroll
    for (int i = 0; i < 8; i++)
        #pragma unroll
        for (int j = 0; j < 8; j++) acc[i][j] = 0.f;

    for (int k0 = 0; k0 < K; k0 += 8) {
        float4 av = *(const float4*)(Ab + (size_t)a_row * lda + k0 + a_col);
        As[a_col+0][a_row] = av.x;
        As[a_col+1][a_row] = av.y;
        As[a_col+2][a_row] = av.z;
        As[a_col+3][a_row] = av.w;
        if (TB) {
            const float* Bb = B + (size_t)(bcol*128 + bt_row) * ldb;
            float4 bv = *(const float4*)(Bb + k0 + bt_col);
            Bs[bt_col+0][bt_row] = bv.x;
            Bs[bt_col+1][bt_row] = bv.y;
            Bs[bt_col+2][bt_row] = bv.z;
            Bs[bt_col+3][bt_row] = bv.w;
        } else {
            const float* Bb = B + (size_t)(k0 + bn_row) * ldb + bcol*128;
            *(float4*)&Bs[bn_row][bn_col] = *(const float4*)(Bb + bn_col);
        }
        __syncthreads();
        #pragma unroll
        for (int k = 0; k < 8; k++) {
            float rm[8], rn[8];
            *(float4*)(rm)   = *(const float4*)&As[k][trow];
            *(float4*)(rm+4) = *(const float4*)&As[k][trow+4];
            *(float4*)(rn)   = *(const float4*)&Bs[k][tcol];
            *(float4*)(rn+4) = *(const float4*)&Bs[k][tcol+4];
            #pragma unroll
            for (int i = 0; i < 8; i++)
                #pragma unroll
                for (int j = 0; j < 8; j++)
                    acc[i][j] = fmaf(rm[i], rn[j], acc[i][j]);
        }
        __syncthreads();
    }

    #pragma unroll
    for (int i = 0; i < 8; i++) {
        size_t row = (size_t)(brow*128 + trow + i);
        #pragma unroll
        for (int j = 0; j < 8; j += 4) {
            int col = bcol*128 + tcol + j;
            float4 o;
            o.x = acc[i][j+0] * scale;
            o.y = acc[i][j+1] * scale;
            o.z = acc[i][j+2] * scale;
            o.w = acc[i][j+3] * scale;
            if (bias) {
                o.x += bias[col+0]; o.y += bias[col+1];
                o.z += bias[col+2]; o.w += bias[col+3];
            }
            *(float4*)(C + row*ldc + col) = o;
        }
    }
}

// ---------------- projection GEMM wrappers (write to device globals) ----------
__global__ void __launch_bounds__(256) k_proj_cq(const float* X, const float* W, const float* b) {
    gemm_tile<false>(X, DD, W, DOWN, b, 1.f, g_cq, DOWN, DD, blockIdx.y, blockIdx.x);
}
__global__ void __launch_bounds__(256) k_proj_ckv(const float* X, const float* W, const float* b) {
    gemm_tile<false>(X, DD, W, DOWN, b, 1.f, g_ckv, DOWN, DD, blockIdx.y, blockIdx.x);
}
__global__ void __launch_bounds__(256) k_proj_kr(const float* X, const float* W, const float* b) {
    gemm_tile<false>(X, DD, W, RR, b, 1.f, g_kr, RR, DD, blockIdx.y, blockIdx.x);
}
__global__ void __launch_bounds__(256) k_proj_qc(const float* W, const float* b) {
    gemm_tile<false>(g_cq, DOWN, W, UP, b, 1.f, g_qc, UP, DOWN, blockIdx.y, blockIdx.x);
}
__global__ void __launch_bounds__(256) k_proj_qr(const float* W, const float* b) {
    gemm_tile<false>(g_cq, DOWN, W, RR*HH, b, 1.f, g_qr, RR*HH, DOWN, blockIdx.y, blockIdx.x);
}
__global__ void __launch_bounds__(256) k_proj_kc(const float* W, const float* b) {
    gemm_tile<false>(g_ckv, DOWN, W, UP, b, 1.f, g_kc, UP, DOWN, blockIdx.y, blockIdx.x);
}
__global__ void __launch_bounds__(256) k_proj_vc(const float* W, const float* b) {
    gemm_tile<false>(g_ckv, DOWN, W, UP, b, 1.f, g_vc, UP, DOWN, blockIdx.y, blockIdx.x);
}
__global__ void __launch_bounds__(256) k_final(const float* W, const float* b, float* out) {
    gemm_tile<false>(g_of, UP, W, DD, b, 1.f, out, DD, DD, blockIdx.y, blockIdx.x);
}

// ---------------- attention GEMMs -------------------------------------------
__global__ void __launch_bounds__(256) k_scores() {
    int z = blockIdx.z;
    gemm_tile<true>(g_qf + (size_t)z*SS*QKDIM, QKDIM,
                    g_kf + (size_t)z*SS*QKDIM, QKDIM,
                    nullptr, INV_SCALE,
                    g_sc + (size_t)z*SS*SS, SS, QKDIM,
                    blockIdx.y, blockIdx.x);
}
__global__ void __launch_bounds__(256) k_pv() {
    int z = blockIdx.y;
    int b = z >> 4, h = z & 15;
    gemm_tile<false>(g_sc + (size_t)z*SS*SS, SS,
                     g_vc + (size_t)b*SS*UP + h*VHD, UP,
                     nullptr, 1.f,
                     g_of + (size_t)b*SS*UP + h*VHD, UP, SS,
                     blockIdx.x, 0);
}

// ---------------- RoPE table + application ----------------------------------
__global__ void k_table() {
    int idx = blockIdx.x * 256 + threadIdx.x;   // 512*256
    int s = idx >> 8;
    int i = idx & 255;
    float div = expf((float)(2*i) * (-9.210340371976184f / (float)RR)); // ln(10000)
    float theta = (float)s * div;
    float sn, cs;
    sincosf(theta, &sn, &cs);
    g_sin[idx] = sn;
    g_cos[idx] = cs;
}

__global__ void k_rope_k() {
    int idx = blockIdx.x * 256 + threadIdx.x;   // MROWS * 256
    int i   = idx & 255;
    int row = idx >> 8;
    int s   = row & (SS-1);
    float2 v = *(const float2*)(g_kr + (size_t)row*RR + 2*i);
    float sn = g_sin[s*256 + i], cs = g_cos[s*256 + i];
    float2 o;
    o.x = v.x*cs - v.y*sn;
    o.y = v.y*cs + v.x*sn;
    *(float2*)(g_krr + (size_t)row*RR + 2*i) = o;
}

// pack q_full[z][s][640]: first 128 = q_c copy, last 512 = rope(q_r)
__global__ void k_pack_q() {
    int idx = blockIdx.x * 256 + threadIdx.x;   // ZB*SS*320 pairs
    int p = idx % 320;
    int s = (idx / 320) & (SS-1);
    int z = idx / (320*SS);
    int b = z >> 4, h = z & 15;
    size_t rowoff = (size_t)(b*SS + s);
    float* dst = g_qf + ((size_t)z*SS + s)*QKDIM;
    if (p < 64) {
        float2 v = *(const float2*)(g_qc + rowoff*UP + h*VHD + 2*p);
        *(float2*)(dst + 2*p) = v;
    } else {
        int i = p - 64;
        float2 v = *(const float2*)(g_qr + rowoff*(RR*HH) + h*RR + 2*i);
        float sn = g_sin[s*256 + i], cs = g_cos[s*256 + i];
        float2 o;
        o.x = v.x*cs - v.y*sn;
        o.y = v.y*cs + v.x*sn;
        *(float2*)(dst + VHD + 2*i) = o;
    }
}

__global__ void k_pack_k() {
    int idx = blockIdx.x * 256 + threadIdx.x;   // ZB*SS*320 pairs
    int p = idx % 320;
    int s = (idx / 320) & (SS-1);
    int z = idx / (320*SS);
    int b = z >> 4, h = z & 15;
    size_t rowoff = (size_t)(b*SS + s);
    float* dst = g_kf + ((size_t)z*SS + s)*QKDIM;
    if (p < 64) {
        float2 v = *(const float2*)(g_kc + rowoff*UP + h*VHD + 2*p);
        *(float2*)(dst + 2*p) = v;
    } else {
        int i = p - 64;
        float2 v = *(const float2*)(g_krr + rowoff*RR + 2*i);  // already roped, h-independent
        *(float2*)(dst + VHD + 2*i) = v;
    }
}

// ---------------- softmax over last axis (512) --------------------------------
__global__ void __launch_bounds__(128) k_softmax() {
    size_t row = blockIdx.x;                    // ZB*SS*... = 128*512 rows... wait: ZB*SS = 65536 rows
    float* p = g_sc + row * SS;
    int t = threadIdx.x;                        // 128 threads, 4 floats each
    float4 v = ((float4*)p)[t];
    float m = fmaxf(fmaxf(v.x, v.y), fmaxf(v.z, v.w));
    #pragma unroll
    for (int o = 16; o; o >>= 1) m = fmaxf(m, __shfl_xor_sync(0xffffffffu, m, o));
    __shared__ float redm[4], reds[4];
    if ((t & 31) == 0) redm[t >> 5] = m;
    __syncthreads();
    m = fmaxf(fmaxf(redm[0], redm[1]), fmaxf(redm[2], redm[3]));
    v.x = __expf(v.x - m); v.y = __expf(v.y - m);
    v.z = __expf(v.z - m); v.w = __expf(v.w - m);
    float s = v.x + v.y + v.z + v.w;
    #pragma unroll
    for (int o = 16; o; o >>= 1) s += __shfl_xor_sync(0xffffffffu, s, o);
    if ((t & 31) == 0) reds[t >> 5] = s;
    __syncthreads();
    s = reds[0] + reds[1] + reds[2] + reds[3];
    float inv = 1.f / s;
    v.x *= inv; v.y *= inv; v.z *= inv; v.w *= inv;
    ((float4*)p)[t] = v;
}

// ---------------- launch ------------------------------------------------------
extern "C" void kernel_launch(void* const* d_in, const int* in_sizes, int n_in,
                              void* d_out, int out_size)
{
    const float* X    = (const float*)d_in[0];
    const float* Wdq  = (const float*)d_in[1];
    const float* bdq  = (const float*)d_in[2];
    const float* Wdkv = (const float*)d_in[3];
    const float* bdkv = (const float*)d_in[4];
    const float* Wuq  = (const float*)d_in[5];
    const float* buq  = (const float*)d_in[6];
    const float* Wuk  = (const float*)d_in[7];
    const float* buk  = (const float*)d_in[8];
    const float* Wuv  = (const float*)d_in[9];
    const float* buv  = (const float*)d_in[10];
    const float* Wqr  = (const float*)d_in[11];
    const float* bqr  = (const float*)d_in[12];
    const float* Wkr  = (const float*)d_in[13];
    const float* bkr  = (const float*)d_in[14];
    const float* Wfc  = (const float*)d_in[15];
    const float* bfc  = (const float*)d_in[16];
    float* out = (float*)d_out;

    // RoPE sin/cos tables: 512 pos x 256 pairs
    k_table<<<(SS*(RR/2))/256, 256>>>();

    // down-projections + rope-k projection (all from X, K=2048)
    k_proj_cq <<<dim3(DOWN/128,  MROWS/128), 256>>>(X, Wdq,  bdq);
    k_proj_ckv<<<dim3(DOWN/128,  MROWS/128), 256>>>(X, Wdkv, bdkv);
    k_proj_kr <<<dim3(RR/128,    MROWS/128), 256>>>(X, Wkr,  bkr);

    // up-projections (K=512)
    k_proj_qc<<<dim3(UP/128,      MROWS/128), 256>>>(Wuq, buq);
    k_proj_qr<<<dim3((RR*HH)/128, MROWS/128), 256>>>(Wqr, bqr);
    k_proj_kc<<<dim3(UP/128,      MROWS/128), 256>>>(Wuk, buk);
    k_proj_vc<<<dim3(UP/128,      MROWS/128), 256>>>(Wuv, buv);

    // rope k_r once (shared across heads), then pack Q/K into [z][s][640]
    k_rope_k<<<(MROWS*(RR/2))/256, 256>>>();
    k_pack_q<<<(ZB*SS*320)/256, 256>>>();
    k_pack_k<<<(ZB*SS*320)/256, 256>>>();

    // attention: scores (QK^T / scale), softmax, PV (scatter into [b,s,h*128+d])
    k_scores <<<dim3(SS/128, SS/128, ZB), 256>>>();
    k_softmax<<<ZB*SS, 128>>>();
    k_pv     <<<dim3(SS/128, ZB), 256>>>();

    // output projection -> d_out
    k_final<<<dim3(DD/128, MROWS/128), 256>>>(Wfc, bfc, out);
}

// round 4
// speedup vs baseline: 2.4768x; 2.4768x over previous
#include <cuda_runtime.h>
#include <cuda_bf16.h>
#include <cstdint>
#include <math.h>

#define BBx   8
#define SSx   512
#define DDx   2048
#define HHx   16
#define DWN   512
#define UPx   2048
#define RRx   512
#define VHDx  128
#define MROWS (BBx*SSx)
#define ZBx   (BBx*HHx)
#define QKD   (VHDx+RRx)
#define NDOWN (DWN*3)
#define INV_SCALE 0.0294627825494394758f

__device__ uint32_t g_xs  [(size_t)MROWS*DDx];
__device__ uint32_t g_wdt [(size_t)NDOWN*DDx];
__device__ float    g_bd  [NDOWN];
__device__ uint32_t g_wuqt[(size_t)UPx*DWN];
__device__ uint32_t g_wukt[(size_t)UPx*DWN];
__device__ uint32_t g_wuvt[(size_t)UPx*DWN];
__device__ uint32_t g_wqrt[(size_t)(RRx*HHx)*DWN];
__device__ uint32_t g_wfct[(size_t)DDx*DDx];
__device__ float    g_d0  [(size_t)MROWS*NDOWN];
__device__ uint32_t g_d0s [(size_t)MROWS*NDOWN];
__device__ float    g_qc  [(size_t)MROWS*UPx];
__device__ float    g_kc  [(size_t)MROWS*UPx];
__device__ float    g_vc  [(size_t)MROWS*UPx];
__device__ float    g_qr  [(size_t)MROWS*RRx*HHx];
__device__ float    g_krr [(size_t)MROWS*RRx];
__device__ uint32_t g_qfs [(size_t)ZBx*SSx*QKD];
__device__ uint32_t g_kfs [(size_t)ZBx*SSx*QKD];
__device__ float    g_sc  [(size_t)ZBx*SSx*SSx];
__device__ uint32_t g_ps  [(size_t)ZBx*SSx*SSx];
__device__ uint32_t g_vts [(size_t)ZBx*VHDx*SSx];
__device__ uint32_t g_ofs [(size_t)MROWS*UPx];
__device__ float    g_sin [SSx*(RRx/2)];
__device__ float    g_cos [SSx*(RRx/2)];

__device__ __forceinline__ uint32_t smem_u32(const void* p) {
    uint32_t a;
    asm("{ .reg .u64 t; cvta.to.shared.u64 t, %1; cvt.u32.u64 %0, t; }" : "=r"(a) : "l"(p));
    return a;
}
__device__ __forceinline__ uint32_t split_pack(float v) {
    __nv_bfloat16 h = __float2bfloat16(v);
    __nv_bfloat16 l = __float2bfloat16(v - __bfloat162float(h));
    return (uint32_t)__bfloat16_as_ushort(h) | ((uint32_t)__bfloat16_as_ushort(l) << 16);
}
__device__ __forceinline__ void ldm4(uint32_t* r, uint32_t addr) {
    asm volatile("ldmatrix.sync.aligned.m8n8.x4.shared.b16 {%0,%1,%2,%3}, [%4];"
        : "=r"(r[0]), "=r"(r[1]), "=r"(r[2]), "=r"(r[3]) : "r"(addr));
}
__device__ __forceinline__ void mma16816(float* c, const uint32_t* a, const uint32_t* b) {
    asm volatile("mma.sync.aligned.m16n8k16.row.col.f32.bf16.bf16.f32 "
        "{%0,%1,%2,%3}, {%4,%5,%6,%7}, {%8,%9}, {%0,%1,%2,%3};"
        : "+f"(c[0]), "+f"(c[1]), "+f"(c[2]), "+f"(c[3])
        : "r"(a[0]), "r"(a[1]), "r"(a[2]), "r"(a[3]), "r"(b[0]), "r"(b[1]));
}

// smem plane: 128 rows x 80B pitch (32 bf16 used) = 10240 B. Planes: Ah, Al, Bh, Bl.
#define PITCH 80
#define PLA_L (128*PITCH)
#define SMEMB (4*PLA_L)

// C = scale*(A @ B^T) + bias.  A:[M,K] packed hi|lo u32, B:[N,K] packed. BM=BN=128, BK=32.
__global__ void __launch_bounds__(256, 1) k_gemm(
    const uint32_t* __restrict__ A, int lda, long long aB,
    const uint32_t* __restrict__ B, int ldb, long long bB,
    float* Cf, uint32_t* Cs, int ldc, long long cO, long long cI,
    const float* __restrict__ bias, float scale, int K)
{
    extern __shared__ __align__(16) char smem[];
    const uint32_t sb = smem_u32(smem);
    const int tid = threadIdx.x, lane = tid & 31, wid = tid >> 5;
    const int wm = wid >> 2, wn = wid & 3;           // 2 x 4 warp grid
    const int z = blockIdx.z, bm = blockIdx.y, bn = blockIdx.x;

    const uint32_t* Ab = A + (size_t)z * aB + (size_t)bm * 128 * lda;
    const uint32_t* Bb = B + (size_t)z * bB + (size_t)bn * 128 * ldb;
    const int nCh = K / 32;

    float acc[4][4][4];
    #pragma unroll
    for (int i = 0; i < 4; i++)
        #pragma unroll
        for (int j = 0; j < 4; j++)
            #pragma unroll
            for (int r = 0; r < 4; r++) acc[i][j][r] = 0.f;

    uint4 pa[4], pb[4];
    // prefetch chunk 0
    #pragma unroll
    for (int p = 0; p < 4; p++) {
        int i = p * 256 + tid, row = i >> 3, kq = (i & 7) * 4;
        pa[p] = *(const uint4*)(Ab + (size_t)row * lda + kq);
        pb[p] = *(const uint4*)(Bb + (size_t)row * ldb + kq);
    }

    for (int c = 0; c < nCh; c++) {
        // stage: unpack hi/lo planes into smem
        #pragma unroll
        for (int p = 0; p < 4; p++) {
            int i = p * 256 + tid, row = i >> 3, kq = (i & 7) * 4;
            int off = row * PITCH + kq * 2;
            uint4 v = pa[p];
            *(uint2*)(smem + off) = make_uint2(
                (v.x & 0xffffu) | (v.y << 16), (v.z & 0xffffu) | (v.w << 16));
            *(uint2*)(smem + PLA_L + off) = make_uint2(
                (v.x >> 16) | (v.y & 0xffff0000u), (v.z >> 16) | (v.w & 0xffff0000u));
            v = pb[p];
            *(uint2*)(smem + 2 * PLA_L + off) = make_uint2(
                (v.x & 0xffffu) | (v.y << 16), (v.z & 0xffffu) | (v.w << 16));
            *(uint2*)(smem + 3 * PLA_L + off) = make_uint2(
                (v.x >> 16) | (v.y & 0xffff0000u), (v.z >> 16) | (v.w & 0xffff0000u));
        }
        __syncthreads();

        // prefetch next chunk while computing this one
        if (c + 1 < nCh) {
            const int kc = (c + 1) * 32;
            #pragma unroll
            for (int p = 0; p < 4; p++) {
                int i = p * 256 + tid, row = i >> 3, kq = (i & 7) * 4;
                pa[p] = *(const uint4*)(Ab + (size_t)row * lda + kc + kq);
                pb[p] = *(const uint4*)(Bb + (size_t)row * ldb + kc + kq);
            }
        }

        #pragma unroll
        for (int k16 = 0; k16 < 2; k16++) {
            uint32_t af[2][4][4];
            uint32_t abase = sb + (wm * 64 + (lane & 15)) * PITCH
                           + (k16 * 16 + (lane >> 4) * 8) * 2;
            #pragma unroll
            for (int mt = 0; mt < 4; mt++) {
                ldm4(af[0][mt], abase + mt * 16 * PITCH);
                ldm4(af[1][mt], abase + PLA_L + mt * 16 * PITCH);
            }
            uint32_t bbase = sb + 2 * PLA_L
                + (wn * 32 + (lane & 7) + ((lane >> 4) << 3)) * PITCH
                + (k16 * 16 + ((lane >> 3) & 1) * 8) * 2;
            #pragma unroll
            for (int nt2 = 0; nt2 < 2; nt2++) {
                uint32_t bh[4], bl[4];
                ldm4(bh, bbase + nt2 * 16 * PITCH);
                ldm4(bl, bbase + PLA_L + nt2 * 16 * PITCH);
                #pragma unroll
                for (int hf = 0; hf < 2; hf++) {
                    const int nt = nt2 * 2 + hf;
                    #pragma unroll
                    for (int mt = 0; mt < 4; mt++) {
                        mma16816(acc[mt][nt], af[0][mt], &bh[2 * hf]);
                        mma16816(acc[mt][nt], af[0][mt], &bl[2 * hf]);
                        mma16816(acc[mt][nt], af[1][mt], &bh[2 * hf]);
                    }
                }
            }
        }
        __syncthreads();
    }

    // epilogue: regs -> global
    const long long coff = (long long)(z >> 4) * cO + (long long)(z & 15) * cI;
    #pragma unroll
    for (int nt = 0; nt < 4; nt++) {
        const int gc = bn * 128 + wn * 32 + nt * 8 + (lane & 3) * 2;
        float2 bv = make_float2(0.f, 0.f);
        if (bias) bv = *(const float2*)(bias + gc);
        #pragma unroll
        for (int mt = 0; mt < 4; mt++) {
            const int r0 = bm * 128 + wm * 64 + mt * 16 + (lane >> 2);
            #pragma unroll
            for (int half = 0; half < 2; half++) {
                const long long gp = coff + (long long)(r0 + half * 8) * ldc + gc;
                float v0 = acc[mt][nt][2 * half + 0] * scale + bv.x;
                float v1 = acc[mt][nt][2 * half + 1] * scale + bv.y;
                if (Cf) *(float2*)(Cf + gp) = make_float2(v0, v1);
                if (Cs) *(uint2*)(Cs + gp) = make_uint2(split_pack(v0), split_pack(v1));
            }
        }
    }
}

__global__ void k_split_x(const float* __restrict__ s, uint32_t* __restrict__ d, int n) {
    int i = blockIdx.x * 256 + threadIdx.x;
    if (i < n) d[i] = split_pack(s[i]);
}
__global__ void k_trsp(const float* __restrict__ W, uint32_t* __restrict__ Wt, int Kd, int Nd) {
    __shared__ float t[32][33];
    int n0 = blockIdx.x * 32, k0 = blockIdx.y * 32;
    int tx = threadIdx.x, ty = threadIdx.y;
    #pragma unroll
    for (int i = 0; i < 32; i += 8)
        t[ty + i][tx] = W[(size_t)(k0 + ty + i) * Nd + n0 + tx];
    __syncthreads();
    #pragma unroll
    for (int i = 0; i < 32; i += 8)
        Wt[(size_t)(n0 + ty + i) * Kd + k0 + tx] = split_pack(t[tx][ty + i]);
}
__global__ void k_biascat(const float* a, const float* b, const float* c) {
    int i = blockIdx.x * 256 + threadIdx.x;
    g_bd[i] = (i < 512) ? a[i] : (i < 1024 ? b[i - 512] : c[i - 1024]);
}
__global__ void k_table() {
    int idx = blockIdx.x * 256 + threadIdx.x;
    int s = idx >> 8, i = idx & 255;
    float dv = expf((float)(2 * i) * (-9.210340371976184f / (float)RRx));
    float sn, cs; sincosf((float)s * dv, &sn, &cs);
    g_sin[idx] = sn; g_cos[idx] = cs;
}
__global__ void k_rope_k() {
    int idx = blockIdx.x * 256 + threadIdx.x;
    int i = idx & 255, row = idx >> 8, s = row & (SSx - 1);
    float2 v = *(const float2*)(g_d0 + (size_t)row * NDOWN + 1024 + 2 * i);
    float sn = g_sin[s * 256 + i], cs = g_cos[s * 256 + i];
    float2 o; o.x = v.x * cs - v.y * sn; o.y = v.y * cs + v.x * sn;
    *(float2*)(g_krr + (size_t)row * RRx + 2 * i) = o;
}
__global__ void k_pack_q() {
    int idx = blockIdx.x * 256 + threadIdx.x;
    int p = idx % 320, s = (idx / 320) & (SSx - 1), z = idx / (320 * SSx);
    int b = z >> 4, h = z & 15;
    size_t ro = (size_t)(b * SSx + s);
    uint32_t* dst = g_qfs + ((size_t)z * SSx + s) * QKD;
    if (p < 64) {
        float2 v = *(const float2*)(g_qc + ro * UPx + h * VHDx + 2 * p);
        dst[2 * p] = split_pack(v.x); dst[2 * p + 1] = split_pack(v.y);
    } else {
        int i = p - 64;
        float2 v = *(const float2*)(g_qr + ro * (RRx * HHx) + h * RRx + 2 * i);
        float sn = g_sin[s * 256 + i], cs = g_cos[s * 256 + i];
        dst[VHDx + 2 * i]     = split_pack(v.x * cs - v.y * sn);
        dst[VHDx + 2 * i + 1] = split_pack(v.y * cs + v.x * sn);
    }
}
__global__ void k_pack_k() {
    int idx = blockIdx.x * 256 + threadIdx.x;
    int p = idx % 320, s = (idx / 320) & (SSx - 1), z = idx / (320 * SSx);
    int b = z >> 4, h = z & 15;
    size_t ro = (size_t)(b * SSx + s);
    uint32_t* dst = g_kfs + ((size_t)z * SSx + s) * QKD;
    if (p < 64) {
        float2 v = *(const float2*)(g_kc + ro * UPx + h * VHDx + 2 * p);
        dst[2 * p] = split_pack(v.x); dst[2 * p + 1] = split_pack(v.y);
    } else {
        int i = p - 64;
        float2 v = *(const float2*)(g_krr + ro * RRx + 2 * i);
        dst[VHDx + 2 * i] = split_pack(v.x); dst[VHDx + 2 * i + 1] = split_pack(v.y);
    }
}
__global__ void k_vt() {
    __shared__ float t[32][33];
    int z = blockIdx.z, b = z >> 4, h = z & 15;
    int s0 = blockIdx.x * 32, d0 = blockIdx.y * 32;
    int tx = threadIdx.x, ty = threadIdx.y;
    #pragma unroll
    for (int i = 0; i < 32; i += 8)
        t[ty + i][tx] = g_vc[(size_t)(b * SSx + s0 + ty + i) * UPx + h * VHDx + d0 + tx];
    __syncthreads();
    #pragma unroll
    for (int i = 0; i < 32; i += 8)
        g_vts[(size_t)z * (VHDx * SSx) + (size_t)(d0 + ty + i) * SSx + s0 + tx] =
            split_pack(t[tx][ty + i]);
}
__global__ void __launch_bounds__(128) k_softmax() {
    size_t row = blockIdx.x;
    const float* p = g_sc + row * SSx;
    uint32_t* q = g_ps + row * SSx;
    int t = threadIdx.x;
    float4 v = ((const float4*)p)[t];
    float m = fmaxf(fmaxf(v.x, v.y), fmaxf(v.z, v.w));
    #pragma unroll
    for (int o = 16; o; o >>= 1) m = fmaxf(m, __shfl_xor_sync(0xffffffffu, m, o));
    __shared__ float rm[4], rs[4];
    if ((t & 31) == 0) rm[t >> 5] = m;
    __syncthreads();
    m = fmaxf(fmaxf(rm[0], rm[1]), fmaxf(rm[2], rm[3]));
    v.x = __expf(v.x - m); v.y = __expf(v.y - m);
    v.z = __expf(v.z - m); v.w = __expf(v.w - m);
    float s = v.x + v.y + v.z + v.w;
    #pragma unroll
    for (int o = 16; o; o >>= 1) s += __shfl_xor_sync(0xffffffffu, s, o);
    if ((t & 31) == 0) rs[t >> 5] = s;
    __syncthreads();
    s = rs[0] + rs[1] + rs[2] + rs[3];
    float inv = 1.f / s;
    uint4 o4;
    o4.x = split_pack(v.x * inv); o4.y = split_pack(v.y * inv);
    o4.z = split_pack(v.z * inv); o4.w = split_pack(v.w * inv);
    ((uint4*)q)[t] = o4;
}

extern "C" void kernel_launch(void* const* d_in, const int* in_sizes, int n_in,
                              void* d_out, int out_size)
{
    const float* X    = (const float*)d_in[0];
    const float* Wdq  = (const float*)d_in[1];
    const float* bdq  = (const float*)d_in[2];
    const float* Wdkv = (const float*)d_in[3];
    const float* bdkv = (const float*)d_in[4];
    const float* Wuq  = (const float*)d_in[5];
    const float* buq  = (const float*)d_in[6];
    const float* Wuk  = (const float*)d_in[7];
    const float* buk  = (const float*)d_in[8];
    const float* Wuv  = (const float*)d_in[9];
    const float* buv  = (const float*)d_in[10];
    const float* Wqr  = (const float*)d_in[11];
    const float* bqr  = (const float*)d_in[12];
    const float* Wkr  = (const float*)d_in[13];
    const float* bkr  = (const float*)d_in[14];
    const float* Wfc  = (const float*)d_in[15];
    const float* bfc  = (const float*)d_in[16];
    float* out = (float*)d_out;

    cudaFuncSetAttribute(k_gemm, cudaFuncAttributeMaxDynamicSharedMemorySize, SMEMB);

    void *p_xs,*p_wdt,*p_bd,*p_wuqt,*p_wukt,*p_wuvt,*p_wqrt,*p_wfct;
    void *p_d0,*p_d0s,*p_qc,*p_kc,*p_vc,*p_qr,*p_qfs,*p_kfs,*p_sc,*p_ps,*p_vts,*p_ofs;
    cudaGetSymbolAddress(&p_xs, g_xs);    cudaGetSymbolAddress(&p_wdt, g_wdt);
    cudaGetSymbolAddress(&p_bd, g_bd);    cudaGetSymbolAddress(&p_wuqt, g_wuqt);
    cudaGetSymbolAddress(&p_wukt, g_wukt);cudaGetSymbolAddress(&p_wuvt, g_wuvt);
    cudaGetSymbolAddress(&p_wqrt, g_wqrt);cudaGetSymbolAddress(&p_wfct, g_wfct);
    cudaGetSymbolAddress(&p_d0, g_d0);    cudaGetSymbolAddress(&p_d0s, g_d0s);
    cudaGetSymbolAddress(&p_qc, g_qc);    cudaGetSymbolAddress(&p_kc, g_kc);
    cudaGetSymbolAddress(&p_vc, g_vc);    cudaGetSymbolAddress(&p_qr, g_qr);
    cudaGetSymbolAddress(&p_qfs, g_qfs);  cudaGetSymbolAddress(&p_kfs, g_kfs);
    cudaGetSymbolAddress(&p_sc, g_sc);    cudaGetSymbolAddress(&p_ps, g_ps);
    cudaGetSymbolAddress(&p_vts, g_vts);  cudaGetSymbolAddress(&p_ofs, g_ofs);

    dim3 tb(32, 8);
    k_table<<<SSx, 256>>>();
    k_split_x<<<(MROWS * DDx) / 256, 256>>>(X, (uint32_t*)p_xs, MROWS * DDx);
    k_trsp<<<dim3(16, 64), tb>>>(Wdq,  (uint32_t*)p_wdt, 2048, 512);
    k_trsp<<<dim3(16, 64), tb>>>(Wdkv, (uint32_t*)p_wdt + (size_t)512 * 2048, 2048, 512);
    k_trsp<<<dim3(16, 64), tb>>>(Wkr,  (uint32_t*)p_wdt + (size_t)1024 * 2048, 2048, 512);
    k_trsp<<<dim3(64, 16), tb>>>(Wuq, (uint32_t*)p_wuqt, 512, 2048);
    k_trsp<<<dim3(64, 16), tb>>>(Wuk, (uint32_t*)p_wukt, 512, 2048);
    k_trsp<<<dim3(64, 16), tb>>>(Wuv, (uint32_t*)p_wuvt, 512, 2048);
    k_trsp<<<dim3(256, 16), tb>>>(Wqr, (uint32_t*)p_wqrt, 512, 8192);
    k_trsp<<<dim3(64, 64), tb>>>(Wfc, (uint32_t*)p_wfct, 2048, 2048);
    k_biascat<<<6, 256>>>(bdq, bdkv, bkr);

    // fused down-proj: M=4096, N=1536, K=2048
    k_gemm<<<dim3(12, 32, 1), 256, SMEMB>>>(
        (uint32_t*)p_xs, DDx, 0, (uint32_t*)p_wdt, DDx, 0,
        (float*)p_d0, (uint32_t*)p_d0s, NDOWN, 0, 0, (float*)p_bd, 1.f, DDx);
    // up-projections, K=512
    k_gemm<<<dim3(16, 32, 1), 256, SMEMB>>>(
        (uint32_t*)p_d0s, NDOWN, 0, (uint32_t*)p_wuqt, DWN, 0,
        (float*)p_qc, nullptr, UPx, 0, 0, buq, 1.f, DWN);
    k_gemm<<<dim3(64, 32, 1), 256, SMEMB>>>(
        (uint32_t*)p_d0s, NDOWN, 0, (uint32_t*)p_wqrt, DWN, 0,
        (float*)p_qr, nullptr, RRx * HHx, 0, 0, bqr, 1.f, DWN);
    k_gemm<<<dim3(16, 32, 1), 256, SMEMB>>>(
        (uint32_t*)p_d0s + 512, NDOWN, 0, (uint32_t*)p_wukt, DWN, 0,
        (float*)p_kc, nullptr, UPx, 0, 0, buk, 1.f, DWN);
    k_gemm<<<dim3(16, 32, 1), 256, SMEMB>>>(
        (uint32_t*)p_d0s + 512, NDOWN, 0, (uint32_t*)p_wuvt, DWN, 0,
        (float*)p_vc, nullptr, UPx, 0, 0, buv, 1.f, DWN);

    k_rope_k<<<MROWS, 256>>>();
    k_pack_q<<<(ZBx * SSx * 320) / 256, 256>>>();
    k_pack_k<<<(ZBx * SSx * 320) / 256, 256>>>();
    k_vt<<<dim3(16, 4, ZBx), tb>>>();

    // scores: per z M=512, N=512, K=640
    k_gemm<<<dim3(4, 4, ZBx), 256, SMEMB>>>(
        (uint32_t*)p_qfs, QKD, (long long)SSx * QKD,
        (uint32_t*)p_kfs, QKD, (long long)SSx * QKD,
        (float*)p_sc, nullptr, SSx, (long long)16 * SSx * SSx, (long long)SSx * SSx,
        nullptr, INV_SCALE, QKD);

    k_softmax<<<ZBx * SSx, 128>>>();

    // PV: per z M=512, N=128, K=512 -> split store scattered to [b,s,h*128+d]
    k_gemm<<<dim3(1, 4, ZBx), 256, SMEMB>>>(
        (uint32_t*)p_ps, SSx, (long long)SSx * SSx,
        (uint32_t*)p_vts, SSx, (long long)VHDx * SSx,
        nullptr, (uint32_t*)p_ofs, UPx, (long long)SSx * UPx, (long long)VHDx,
        nullptr, 1.f, SSx);

    // final: M=4096, N=2048, K=2048 -> out fp32
    k_gemm<<<dim3(16, 32, 1), 256, SMEMB>>>(
        (uint32_t*)p_ofs, UPx, 0, (uint32_t*)p_wfct, DDx, 0,
        out, nullptr, DDx, 0, 0, bfc, 1.f, DDx);
}

// round 5
// speedup vs baseline: 2.4950x; 1.0073x over previous
#include <cuda_runtime.h>
#include <cuda_bf16.h>
#include <cstdint>
#include <math.h>

#define BBx   8
#define SSx   512
#define DDx   2048
#define HHx   16
#define DWN   512
#define UPx   2048
#define RRx   512
#define VHDx  128
#define MROWS (BBx*SSx)
#define ZBx   (BBx*HHx)
#define QKD   (VHDx+RRx)
#define NDOWN (DWN*3)
#define INV_SCALE 0.0294627825494394758f

// hi/lo bf16 planes stored separately (pure-copy staging for cp.async)
__device__ uint16_t g_xsh [(size_t)MROWS*DDx];
__device__ uint16_t g_xsl [(size_t)MROWS*DDx];
__device__ uint16_t g_wdth[(size_t)NDOWN*DDx];
__device__ uint16_t g_wdtl[(size_t)NDOWN*DDx];
__device__ float    g_bd  [NDOWN];
__device__ uint16_t g_wuqth[(size_t)UPx*DWN];
__device__ uint16_t g_wuqtl[(size_t)UPx*DWN];
__device__ uint16_t g_wukth[(size_t)UPx*DWN];
__device__ uint16_t g_wuktl[(size_t)UPx*DWN];
__device__ uint16_t g_wuvth[(size_t)UPx*DWN];
__device__ uint16_t g_wuvtl[(size_t)UPx*DWN];
__device__ uint16_t g_wqrth[(size_t)(RRx*HHx)*DWN];
__device__ uint16_t g_wqrtl[(size_t)(RRx*HHx)*DWN];
__device__ uint16_t g_wfcth[(size_t)DDx*DDx];
__device__ uint16_t g_wfctl[(size_t)DDx*DDx];
__device__ float    g_d0  [(size_t)MROWS*NDOWN];
__device__ uint16_t g_d0sh[(size_t)MROWS*NDOWN];
__device__ uint16_t g_d0sl[(size_t)MROWS*NDOWN];
__device__ float    g_qc  [(size_t)MROWS*UPx];
__device__ float    g_kc  [(size_t)MROWS*UPx];
__device__ float    g_vc  [(size_t)MROWS*UPx];
__device__ float    g_qr  [(size_t)MROWS*RRx*HHx];
__device__ float    g_krr [(size_t)MROWS*RRx];
__device__ uint16_t g_qfsh[(size_t)ZBx*SSx*QKD];
__device__ uint16_t g_qfsl[(size_t)ZBx*SSx*QKD];
__device__ uint16_t g_kfsh[(size_t)ZBx*SSx*QKD];
__device__ uint16_t g_kfsl[(size_t)ZBx*SSx*QKD];
__device__ float    g_sc  [(size_t)ZBx*SSx*SSx];
__device__ uint16_t g_psh [(size_t)ZBx*SSx*SSx];
__device__ uint16_t g_psl [(size_t)ZBx*SSx*SSx];
__device__ uint16_t g_vtsh[(size_t)ZBx*VHDx*SSx];
__device__ uint16_t g_vtsl[(size_t)ZBx*VHDx*SSx];
__device__ uint16_t g_ofsh[(size_t)MROWS*UPx];
__device__ uint16_t g_ofsl[(size_t)MROWS*UPx];
__device__ float    g_sin [SSx*(RRx/2)];
__device__ float    g_cos [SSx*(RRx/2)];

__device__ __forceinline__ uint32_t smem_u32(const void* p) {
    uint32_t a;
    asm("{ .reg .u64 t; cvta.to.shared.u64 t, %1; cvt.u32.u64 %0, t; }" : "=r"(a) : "l"(p));
    return a;
}
__device__ __forceinline__ void split1(float v, uint16_t& h, uint16_t& l) {
    __nv_bfloat16 hb = __float2bfloat16(v);
    __nv_bfloat16 lb = __float2bfloat16(v - __bfloat162float(hb));
    h = __bfloat16_as_ushort(hb); l = __bfloat16_as_ushort(lb);
}
__device__ __forceinline__ uint2 split2(float a, float b) {
    uint16_t ah, al, bh, bl; split1(a, ah, al); split1(b, bh, bl);
    return make_uint2((uint32_t)ah | ((uint32_t)bh << 16),
                      (uint32_t)al | ((uint32_t)bl << 16));
}
__device__ __forceinline__ void ldm4(uint32_t* r, uint32_t addr) {
    asm volatile("ldmatrix.sync.aligned.m8n8.x4.shared.b16 {%0,%1,%2,%3}, [%4];"
        : "=r"(r[0]), "=r"(r[1]), "=r"(r[2]), "=r"(r[3]) : "r"(addr));
}
__device__ __forceinline__ void mma16816(float* c, const uint32_t* a, const uint32_t* b) {
    asm volatile("mma.sync.aligned.m16n8k16.row.col.f32.bf16.bf16.f32 "
        "{%0,%1,%2,%3}, {%4,%5,%6,%7}, {%8,%9}, {%0,%1,%2,%3};"
        : "+f"(c[0]), "+f"(c[1]), "+f"(c[2]), "+f"(c[3])
        : "r"(a[0]), "r"(a[1]), "r"(a[2]), "r"(a[3]), "r"(b[0]), "r"(b[1]));
}
#define CP16(dst, src) \
    asm volatile("cp.async.cg.shared.global [%0], [%1], 16;" :: "r"(dst), "l"(src))
#define CP_COMMIT() asm volatile("cp.async.commit_group;" ::: "memory")
#define CP_WAIT1()  asm volatile("cp.async.wait_group 1;" ::: "memory")

// smem plane: 128 rows x 80B pitch (64B payload = 32 bf16). Planes: Ah, Al, Bh, Bl.
#define PITCH  80
#define PLA_L  (128*PITCH)
#define STG_L  (4*PLA_L)          // 40960 per stage
#define STAGES 3
#define SMEMB  (STAGES*STG_L)     // 122880

// C = scale*(A @ B^T) + bias.  A,B given as hi/lo bf16 planes. BM=BN=128, BK=32.
__global__ void __launch_bounds__(256, 1) k_gemm(
    const uint16_t* __restrict__ Ah, const uint16_t* __restrict__ Al, int lda, long long aB,
    const uint16_t* __restrict__ Bh, const uint16_t* __restrict__ Bl, int ldb, long long bB,
    float* Cf, uint16_t* Csh, uint16_t* Csl, int ldc, long long cO, long long cI,
    const float* __restrict__ bias, float scale, int K)
{
    extern __shared__ __align__(16) char smem[];
    const uint32_t sb = smem_u32(smem);
    const int tid = threadIdx.x, lane = tid & 31, wid = tid >> 5;
    const int wm = wid >> 2, wn = wid & 3;
    const int z = blockIdx.z, bm = blockIdx.y, bn = blockIdx.x;

    const uint16_t* pb0 = Ah + (size_t)z * aB + (size_t)bm * 128 * lda;
    const uint16_t* pb1 = Al + (size_t)z * aB + (size_t)bm * 128 * lda;
    const uint16_t* pb2 = Bh + (size_t)z * bB + (size_t)bn * 128 * ldb;
    const uint16_t* pb3 = Bl + (size_t)z * bB + (size_t)bn * 128 * ldb;
    const int nCh = K / 32;

    const int crow = tid >> 2, cq = (tid & 3) * 16;     // copy row within half-plane pair
    // per-plane copy: 512 x 16B ops; thread handles p=0..7, plane = p>>1
    auto issue = [&](int c) {
        if (c < nCh) {
            const int kc = c * 32;
            const uint32_t sdst = sb + (c % STAGES) * STG_L;
            #pragma unroll
            for (int p = 0; p < 8; p++) {
                const int pl = p >> 1;
                const int r = (p & 1) * 64 + (crow & 63);
                const int rr = (tid >> 2) >= 64 ? r + 0 : r;   // crow in 0..63
                (void)rr;
                const uint16_t* src;
                int ld = (pl < 2) ? lda : ldb;
                src = (pl == 0 ? pb0 : pl == 1 ? pb1 : pl == 2 ? pb2 : pb3);
                const int row = (p & 1) * 64 + (tid >> 2);
                CP16(sdst + pl * PLA_L + row * PITCH + (tid & 3) * 16,
                     src + (size_t)row * ld + kc + (tid & 3) * 8);
            }
        }
        CP_COMMIT();
    };

    float acc[4][4][4];
    #pragma unroll
    for (int i = 0; i < 4; i++)
        #pragma unroll
        for (int j = 0; j < 4; j++)
            #pragma unroll
            for (int r = 0; r < 4; r++) acc[i][j][r] = 0.f;

    issue(0); issue(1);

    for (int c = 0; c < nCh; c++) {
        CP_WAIT1();
        __syncthreads();
        issue(c + 2);

        const uint32_t sbuf = sb + (c % STAGES) * STG_L;
        #pragma unroll
        for (int k16 = 0; k16 < 2; k16++) {
            uint32_t af[2][4][4];
            uint32_t abase = sbuf + (wm * 64 + (lane & 15)) * PITCH
                           + (k16 * 16 + (lane >> 4) * 8) * 2;
            #pragma unroll
            for (int mt = 0; mt < 4; mt++) {
                ldm4(af[0][mt], abase + mt * 16 * PITCH);
                ldm4(af[1][mt], abase + PLA_L + mt * 16 * PITCH);
            }
            uint32_t bbase = sbuf + 2 * PLA_L
                + (wn * 32 + (lane & 7) + ((lane >> 4) << 3)) * PITCH
                + (k16 * 16 + ((lane >> 3) & 1) * 8) * 2;
            #pragma unroll
            for (int nt2 = 0; nt2 < 2; nt2++) {
                uint32_t bh[4], bl[4];
                ldm4(bh, bbase + nt2 * 16 * PITCH);
                ldm4(bl, bbase + PLA_L + nt2 * 16 * PITCH);
                #pragma unroll
                for (int hf = 0; hf < 2; hf++) {
                    const int nt = nt2 * 2 + hf;
                    #pragma unroll
                    for (int mt = 0; mt < 4; mt++) {
                        mma16816(acc[mt][nt], af[0][mt], &bh[2 * hf]);
                        mma16816(acc[mt][nt], af[0][mt], &bl[2 * hf]);
                        mma16816(acc[mt][nt], af[1][mt], &bh[2 * hf]);
                    }
                }
            }
        }
        __syncthreads();
    }

    // epilogue
    const long long coff = (long long)(z >> 4) * cO + (long long)(z & 15) * cI;
    #pragma unroll
    for (int nt = 0; nt < 4; nt++) {
        const int gc = bn * 128 + wn * 32 + nt * 8 + (lane & 3) * 2;
        float2 bv = make_float2(0.f, 0.f);
        if (bias) bv = *(const float2*)(bias + gc);
        #pragma unroll
        for (int mt = 0; mt < 4; mt++) {
            const int r0 = bm * 128 + wm * 64 + mt * 16 + (lane >> 2);
            #pragma unroll
            for (int half = 0; half < 2; half++) {
                const long long gp = coff + (long long)(r0 + half * 8) * ldc + gc;
                float v0 = acc[mt][nt][2 * half + 0] * scale + bv.x;
                float v1 = acc[mt][nt][2 * half + 1] * scale + bv.y;
                if (Cf) *(float2*)(Cf + gp) = make_float2(v0, v1);
                if (Csh) {
                    uint2 s = split2(v0, v1);
                    *(uint32_t*)(Csh + gp) = s.x;
                    *(uint32_t*)(Csl + gp) = s.y;
                }
            }
        }
    }
}

__global__ void k_split_x(const float* __restrict__ s, uint16_t* __restrict__ dh,
                          uint16_t* __restrict__ dl, int n2) {
    int i = blockIdx.x * 256 + threadIdx.x;
    if (i < n2) {
        float2 v = *(const float2*)(s + 2 * i);
        uint2 sp = split2(v.x, v.y);
        *(uint32_t*)(dh + 2 * i) = sp.x;
        *(uint32_t*)(dl + 2 * i) = sp.y;
    }
}
__global__ void k_trsp(const float* __restrict__ W, uint16_t* __restrict__ Wth,
                       uint16_t* __restrict__ Wtl, int Kd, int Nd) {
    __shared__ float t[32][33];
    int n0 = blockIdx.x * 32, k0 = blockIdx.y * 32;
    int tx = threadIdx.x, ty = threadIdx.y;
    #pragma unroll
    for (int i = 0; i < 32; i += 8)
        t[ty + i][tx] = W[(size_t)(k0 + ty + i) * Nd + n0 + tx];
    __syncthreads();
    #pragma unroll
    for (int i = 0; i < 32; i += 8) {
        uint16_t h, l; split1(t[tx][ty + i], h, l);
        size_t o = (size_t)(n0 + ty + i) * Kd + k0 + tx;
        Wth[o] = h; Wtl[o] = l;
    }
}
__global__ void k_biascat(const float* a, const float* b, const float* c) {
    int i = blockIdx.x * 256 + threadIdx.x;
    g_bd[i] = (i < 512) ? a[i] : (i < 1024 ? b[i - 512] : c[i - 1024]);
}
__global__ void k_table() {
    int idx = blockIdx.x * 256 + threadIdx.x;
    int s = idx >> 8, i = idx & 255;
    float dv = expf((float)(2 * i) * (-9.210340371976184f / (float)RRx));
    float sn, cs; sincosf((float)s * dv, &sn, &cs);
    g_sin[idx] = sn; g_cos[idx] = cs;
}
__global__ void k_rope_k() {
    int idx = blockIdx.x * 256 + threadIdx.x;
    int i = idx & 255, row = idx >> 8, s = row & (SSx - 1);
    float2 v = *(const float2*)(g_d0 + (size_t)row * NDOWN + 1024 + 2 * i);
    float sn = g_sin[s * 256 + i], cs = g_cos[s * 256 + i];
    float2 o; o.x = v.x * cs - v.y * sn; o.y = v.y * cs + v.x * sn;
    *(float2*)(g_krr + (size_t)row * RRx + 2 * i) = o;
}
__global__ void k_pack_q() {
    int idx = blockIdx.x * 256 + threadIdx.x;
    int p = idx % 320, s = (idx / 320) & (SSx - 1), z = idx / (320 * SSx);
    int b = z >> 4, h = z & 15;
    size_t ro = (size_t)(b * SSx + s);
    size_t base = ((size_t)z * SSx + s) * QKD;
    if (p < 64) {
        float2 v = *(const float2*)(g_qc + ro * UPx + h * VHDx + 2 * p);
        uint2 sp = split2(v.x, v.y);
        *(uint32_t*)(g_qfsh + base + 2 * p) = sp.x;
        *(uint32_t*)(g_qfsl + base + 2 * p) = sp.y;
    } else {
        int i = p - 64;
        float2 v = *(const float2*)(g_qr + ro * (RRx * HHx) + h * RRx + 2 * i);
        float sn = g_sin[s * 256 + i], cs = g_cos[s * 256 + i];
        uint2 sp = split2(v.x * cs - v.y * sn, v.y * cs + v.x * sn);
        *(uint32_t*)(g_qfsh + base + VHDx + 2 * i) = sp.x;
        *(uint32_t*)(g_qfsl + base + VHDx + 2 * i) = sp.y;
    }
}
__global__ void k_pack_k() {
    int idx = blockIdx.x * 256 + threadIdx.x;
    int p = idx % 320, s = (idx / 320) & (SSx - 1), z = idx / (320 * SSx);
    int b = z >> 4, h = z & 15;
    size_t ro = (size_t)(b * SSx + s);
    size_t base = ((size_t)z * SSx + s) * QKD;
    if (p < 64) {
        float2 v = *(const float2*)(g_kc + ro * UPx + h * VHDx + 2 * p);
        uint2 sp = split2(v.x, v.y);
        *(uint32_t*)(g_kfsh + base + 2 * p) = sp.x;
        *(uint32_t*)(g_kfsl + base + 2 * p) = sp.y;
    } else {
        int i = p - 64;
        float2 v = *(const float2*)(g_krr + ro * RRx + 2 * i);
        uint2 sp = split2(v.x, v.y);
        *(uint32_t*)(g_kfsh + base + VHDx + 2 * i) = sp.x;
        *(uint32_t*)(g_kfsl + base + VHDx + 2 * i) = sp.y;
    }
}
__global__ void k_vt() {
    __shared__ float t[32][33];
    int z = blockIdx.z, b = z >> 4, h = z & 15;
    int s0 = blockIdx.x * 32, d0 = blockIdx.y * 32;
    int tx = threadIdx.x, ty = threadIdx.y;
    #pragma unroll
    for (int i = 0; i < 32; i += 8)
        t[ty + i][tx] = g_vc[(size_t)(b * SSx + s0 + ty + i) * UPx + h * VHDx + d0 + tx];
    __syncthreads();
    #pragma unroll
    for (int i = 0; i < 32; i += 8) {
        uint16_t hh, ll; split1(t[tx][ty + i], hh, ll);
        size_t o = (size_t)z * (VHDx * SSx) + (size_t)(d0 + ty + i) * SSx + s0 + tx;
        g_vtsh[o] = hh; g_vtsl[o] = ll;
    }
}
__global__ void __launch_bounds__(128) k_softmax() {
    size_t row = blockIdx.x;
    const float* p = g_sc + row * SSx;
    int t = threadIdx.x;
    float4 v = ((const float4*)p)[t];
    float m = fmaxf(fmaxf(v.x, v.y), fmaxf(v.z, v.w));
    #pragma unroll
    for (int o = 16; o; o >>= 1) m = fmaxf(m, __shfl_xor_sync(0xffffffffu, m, o));
    __shared__ float rm[4], rs[4];
    if ((t & 31) == 0) rm[t >> 5] = m;
    __syncthreads();
    m = fmaxf(fmaxf(rm[0], rm[1]), fmaxf(rm[2], rm[3]));
    v.x = __expf(v.x - m); v.y = __expf(v.y - m);
    v.z = __expf(v.z - m); v.w = __expf(v.w - m);
    float s = v.x + v.y + v.z + v.w;
    #pragma unroll
    for (int o = 16; o; o >>= 1) s += __shfl_xor_sync(0xffffffffu, s, o);
    if ((t & 31) == 0) rs[t >> 5] = s;
    __syncthreads();
    s = rs[0] + rs[1] + rs[2] + rs[3];
    float inv = 1.f / s;
    uint2 s01 = split2(v.x * inv, v.y * inv);
    uint2 s23 = split2(v.z * inv, v.w * inv);
    *(uint2*)(g_psh + row * SSx + t * 4) = make_uint2(s01.x, s23.x);
    *(uint2*)(g_psl + row * SSx + t * 4) = make_uint2(s01.y, s23.y);
}

extern "C" void kernel_launch(void* const* d_in, const int* in_sizes, int n_in,
                              void* d_out, int out_size)
{
    const float* X    = (const float*)d_in[0];
    const float* Wdq  = (const float*)d_in[1];
    const float* bdq  = (const float*)d_in[2];
    const float* Wdkv = (const float*)d_in[3];
    const float* bdkv = (const float*)d_in[4];
    const float* Wuq  = (const float*)d_in[5];
    const float* buq  = (const float*)d_in[6];
    const float* Wuk  = (const float*)d_in[7];
    const float* buk  = (const float*)d_in[8];
    const float* Wuv  = (const float*)d_in[9];
    const float* buv  = (const float*)d_in[10];
    const float* Wqr  = (const float*)d_in[11];
    const float* bqr  = (const float*)d_in[12];
    const float* Wkr  = (const float*)d_in[13];
    const float* bkr  = (const float*)d_in[14];
    const float* Wfc  = (const float*)d_in[15];
    const float* bfc  = (const float*)d_in[16];
    float* out = (float*)d_out;

    cudaFuncSetAttribute(k_gemm, cudaFuncAttributeMaxDynamicSharedMemorySize, SMEMB);

    #define SYM(v, g) void* v; cudaGetSymbolAddress(&v, g)
    SYM(p_xsh, g_xsh);   SYM(p_xsl, g_xsl);
    SYM(p_wdth, g_wdth); SYM(p_wdtl, g_wdtl); SYM(p_bd, g_bd);
    SYM(p_wuqth, g_wuqth); SYM(p_wuqtl, g_wuqtl);
    SYM(p_wukth, g_wukth); SYM(p_wuktl, g_wuktl);
    SYM(p_wuvth, g_wuvth); SYM(p_wuvtl, g_wuvtl);
    SYM(p_wqrth, g_wqrth); SYM(p_wqrtl, g_wqrtl);
    SYM(p_wfcth, g_wfcth); SYM(p_wfctl, g_wfctl);
    SYM(p_d0, g_d0); SYM(p_d0sh, g_d0sh); SYM(p_d0sl, g_d0sl);
    SYM(p_qc, g_qc); SYM(p_kc, g_kc); SYM(p_vc, g_vc); SYM(p_qr, g_qr);
    SYM(p_qfsh, g_qfsh); SYM(p_qfsl, g_qfsl);
    SYM(p_kfsh, g_kfsh); SYM(p_kfsl, g_kfsl);
    SYM(p_sc, g_sc); SYM(p_psh, g_psh); SYM(p_psl, g_psl);
    SYM(p_vtsh, g_vtsh); SYM(p_vtsl, g_vtsl);
    SYM(p_ofsh, g_ofsh); SYM(p_ofsl, g_ofsl);
    #undef SYM

    dim3 tb(32, 8);
    k_table<<<SSx, 256>>>();
    k_split_x<<<(MROWS * DDx / 2) / 256, 256>>>(X, (uint16_t*)p_xsh, (uint16_t*)p_xsl,
                                                MROWS * DDx / 2);
    k_trsp<<<dim3(16, 64), tb>>>(Wdq,  (uint16_t*)p_wdth, (uint16_t*)p_wdtl, 2048, 512);
    k_trsp<<<dim3(16, 64), tb>>>(Wdkv, (uint16_t*)p_wdth + (size_t)512 * 2048,
                                       (uint16_t*)p_wdtl + (size_t)512 * 2048, 2048, 512);
    k_trsp<<<dim3(16, 64), tb>>>(Wkr,  (uint16_t*)p_wdth + (size_t)1024 * 2048,
                                       (uint16_t*)p_wdtl + (size_t)1024 * 2048, 2048, 512);
    k_trsp<<<dim3(64, 16), tb>>>(Wuq, (uint16_t*)p_wuqth, (uint16_t*)p_wuqtl, 512, 2048);
    k_trsp<<<dim3(64, 16), tb>>>(Wuk, (uint16_t*)p_wukth, (uint16_t*)p_wuktl, 512, 2048);
    k_trsp<<<dim3(64, 16), tb>>>(Wuv, (uint16_t*)p_wuvth, (uint16_t*)p_wuvtl, 512, 2048);
    k_trsp<<<dim3(256, 16), tb>>>(Wqr, (uint16_t*)p_wqrth, (uint16_t*)p_wqrtl, 512, 8192);
    k_trsp<<<dim3(64, 64), tb>>>(Wfc, (uint16_t*)p_wfcth, (uint16_t*)p_wfctl, 2048, 2048);
    k_biascat<<<6, 256>>>(bdq, bdkv, bkr);

    // fused down-proj: M=4096, N=1536, K=2048
    k_gemm<<<dim3(12, 32, 1), 256, SMEMB>>>(
        (uint16_t*)p_xsh, (uint16_t*)p_xsl, DDx, 0,
        (uint16_t*)p_wdth, (uint16_t*)p_wdtl, DDx, 0,
        (float*)p_d0, (uint16_t*)p_d0sh, (uint16_t*)p_d0sl, NDOWN, 0, 0,
        (float*)p_bd, 1.f, DDx);
    // up-projections, K=512
    k_gemm<<<dim3(16, 32, 1), 256, SMEMB>>>(
        (uint16_t*)p_d0sh, (uint16_t*)p_d0sl, NDOWN, 0,
        (uint16_t*)p_wuqth, (uint16_t*)p_wuqtl, DWN, 0,
        (float*)p_qc, nullptr, nullptr, UPx, 0, 0, buq, 1.f, DWN);
    k_gemm<<<dim3(64, 32, 1), 256, SMEMB>>>(
        (uint16_t*)p_d0sh, (uint16_t*)p_d0sl, NDOWN, 0,
        (uint16_t*)p_wqrth, (uint16_t*)p_wqrtl, DWN, 0,
        (float*)p_qr, nullptr, nullptr, RRx * HHx, 0, 0, bqr, 1.f, DWN);
    k_gemm<<<dim3(16, 32, 1), 256, SMEMB>>>(
        (uint16_t*)p_d0sh + 512, (uint16_t*)p_d0sl + 512, NDOWN, 0,
        (uint16_t*)p_wukth, (uint16_t*)p_wuktl, DWN, 0,
        (float*)p_kc, nullptr, nullptr, UPx, 0, 0, buk, 1.f, DWN);
    k_gemm<<<dim3(16, 32, 1), 256, SMEMB>>>(
        (uint16_t*)p_d0sh + 512, (uint16_t*)p_d0sl + 512, NDOWN, 0,
        (uint16_t*)p_wuvth, (uint16_t*)p_wuvtl, DWN, 0,
        (float*)p_vc, nullptr, nullptr, UPx, 0, 0, buv, 1.f, DWN);

    k_rope_k<<<MROWS, 256>>>();
    k_pack_q<<<(ZBx * SSx * 320) / 256, 256>>>();
    k_pack_k<<<(ZBx * SSx * 320) / 256, 256>>>();
    k_vt<<<dim3(16, 4, ZBx), tb>>>();

    // scores: per z M=512, N=512, K=640
    k_gemm<<<dim3(4, 4, ZBx), 256, SMEMB>>>(
        (uint16_t*)p_qfsh, (uint16_t*)p_qfsl, QKD, (long long)SSx * QKD,
        (uint16_t*)p_kfsh, (uint16_t*)p_kfsl, QKD, (long long)SSx * QKD,
        (float*)p_sc, nullptr, nullptr, SSx,
        (long long)16 * SSx * SSx, (long long)SSx * SSx,
        nullptr, INV_SCALE, QKD);

    k_softmax<<<ZBx * SSx, 128>>>();

    // PV: per z M=512, N=128, K=512 -> split store scattered to [b,s,h*128+d]
    k_gemm<<<dim3(1, 4, ZBx), 256, SMEMB>>>(
        (uint16_t*)p_psh, (uint16_t*)p_psl, SSx, (long long)SSx * SSx,
        (uint16_t*)p_vtsh, (uint16_t*)p_vtsl, SSx, (long long)VHDx * SSx,
        nullptr, (uint16_t*)p_ofsh, (uint16_t*)p_ofsl, UPx,
        (long long)SSx * UPx, (long long)VHDx,
        nullptr, 1.f, SSx);

    // final: M=4096, N=2048, K=2048 -> out fp32
    k_gemm<<<dim3(16, 32, 1), 256, SMEMB>>>(
        (uint16_t*)p_ofsh, (uint16_t*)p_ofsl, UPx, 0,
        (uint16_t*)p_wfcth, (uint16_t*)p_wfctl, DDx, 0,
        out, nullptr, nullptr, DDx, 0, 0, bfc, 1.f, DDx);
}

// round 6
// speedup vs baseline: 2.7440x; 1.0998x over previous
#include <cuda_runtime.h>
#include <cuda_bf16.h>
#include <cstdint>
#include <math.h>

#define BBx   8
#define SSx   512
#define DDx   2048
#define HHx   16
#define DWN   512
#define UPx   2048
#define RRx   512
#define VHDx  128
#define MROWS (BBx*SSx)
#define ZBx   (BBx*HHx)
#define QKD   (VHDx+RRx)
#define NDOWN (DWN*3)
#define INV_SCALE 0.0294627825494394758f

// hi/lo bf16 planes stored separately (pure-copy staging for cp.async)
__device__ uint16_t g_xsh [(size_t)MROWS*DDx];
__device__ uint16_t g_xsl [(size_t)MROWS*DDx];
__device__ uint16_t g_wdth[(size_t)NDOWN*DDx];
__device__ uint16_t g_wdtl[(size_t)NDOWN*DDx];
__device__ float    g_bd  [NDOWN];
__device__ uint16_t g_wuqth[(size_t)UPx*DWN];
__device__ uint16_t g_wuqtl[(size_t)UPx*DWN];
__device__ uint16_t g_wukth[(size_t)UPx*DWN];
__device__ uint16_t g_wuktl[(size_t)UPx*DWN];
__device__ uint16_t g_wuvth[(size_t)UPx*DWN];
__device__ uint16_t g_wuvtl[(size_t)UPx*DWN];
__device__ uint16_t g_wqrth[(size_t)(RRx*HHx)*DWN];
__device__ uint16_t g_wqrtl[(size_t)(RRx*HHx)*DWN];
__device__ uint16_t g_wfcth[(size_t)DDx*DDx];
__device__ uint16_t g_wfctl[(size_t)DDx*DDx];
__device__ uint16_t g_d0sh[(size_t)MROWS*NDOWN];
__device__ uint16_t g_d0sl[(size_t)MROWS*NDOWN];
__device__ float    g_qc  [(size_t)MROWS*UPx];
__device__ float    g_kc  [(size_t)MROWS*UPx];
__device__ float    g_vc  [(size_t)MROWS*UPx];
__device__ float    g_qr  [(size_t)MROWS*RRx*HHx];
__device__ float    g_krr [(size_t)MROWS*RRx];
__device__ uint16_t g_qfsh[(size_t)ZBx*SSx*QKD];
__device__ uint16_t g_qfsl[(size_t)ZBx*SSx*QKD];
__device__ uint16_t g_kfsh[(size_t)ZBx*SSx*QKD];
__device__ uint16_t g_kfsl[(size_t)ZBx*SSx*QKD];
__device__ float    g_sc  [(size_t)ZBx*SSx*SSx];
__device__ uint16_t g_psh [(size_t)ZBx*SSx*SSx];
__device__ uint16_t g_psl [(size_t)ZBx*SSx*SSx];
__device__ uint16_t g_vtsh[(size_t)ZBx*VHDx*SSx];
__device__ uint16_t g_vtsl[(size_t)ZBx*VHDx*SSx];
__device__ uint16_t g_ofsh[(size_t)MROWS*UPx];
__device__ uint16_t g_ofsl[(size_t)MROWS*UPx];
__device__ float    g_sin [SSx*(RRx/2)];
__device__ float    g_cos [SSx*(RRx/2)];

__device__ __forceinline__ uint32_t smem_u32(const void* p) {
    uint32_t a;
    asm("{ .reg .u64 t; cvta.to.shared.u64 t, %1; cvt.u32.u64 %0, t; }" : "=r"(a) : "l"(p));
    return a;
}
__device__ __forceinline__ void split1(float v, uint16_t& h, uint16_t& l) {
    __nv_bfloat16 hb = __float2bfloat16(v);
    __nv_bfloat16 lb = __float2bfloat16(v - __bfloat162float(hb));
    h = __bfloat16_as_ushort(hb); l = __bfloat16_as_ushort(lb);
}
__device__ __forceinline__ uint2 split2(float a, float b) {
    uint16_t ah, al, bh, bl; split1(a, ah, al); split1(b, bh, bl);
    return make_uint2((uint32_t)ah | ((uint32_t)bh << 16),
                      (uint32_t)al | ((uint32_t)bl << 16));
}
__device__ __forceinline__ float join1(uint16_t h, uint16_t l) {
    return __bfloat162float(__ushort_as_bfloat16(h)) +
           __bfloat162float(__ushort_as_bfloat16(l));
}
__device__ __forceinline__ void ldm4(uint32_t* r, uint32_t addr) {
    asm volatile("ldmatrix.sync.aligned.m8n8.x4.shared.b16 {%0,%1,%2,%3}, [%4];"
        : "=r"(r[0]), "=r"(r[1]), "=r"(r[2]), "=r"(r[3]) : "r"(addr));
}
__device__ __forceinline__ void mma16816(float* c, const uint32_t* a, const uint32_t* b) {
    asm volatile("mma.sync.aligned.m16n8k16.row.col.f32.bf16.bf16.f32 "
        "{%0,%1,%2,%3}, {%4,%5,%6,%7}, {%8,%9}, {%0,%1,%2,%3};"
        : "+f"(c[0]), "+f"(c[1]), "+f"(c[2]), "+f"(c[3])
        : "r"(a[0]), "r"(a[1]), "r"(a[2]), "r"(a[3]), "r"(b[0]), "r"(b[1]));
}
#define CP16(dst, src) \
    asm volatile("cp.async.cg.shared.global [%0], [%1], 16;" :: "r"(dst), "l"(src))
#define CP_COMMIT() asm volatile("cp.async.commit_group;" ::: "memory")
#define CP_WAIT1()  asm volatile("cp.async.wait_group 1;" ::: "memory")

// smem plane: 128 rows x 80B pitch (64B payload = 32 bf16). Planes: Ah, Al, Bh, Bl.
#define PITCH  80
#define PLA_L  (128*PITCH)
#define STG_L  (4*PLA_L)          // 40960 per stage
#define STAGES 2
#define SMEMB  (STAGES*STG_L)     // 81920 -> 2 CTAs/SM

// C = scale*(A @ B^T) + bias.  A,B given as hi/lo bf16 planes. BM=BN=128, BK=32.
__global__ void __launch_bounds__(256, 2) k_gemm(
    const uint16_t* __restrict__ Ah, const uint16_t* __restrict__ Al, int lda, long long aB,
    const uint16_t* __restrict__ Bh, const uint16_t* __restrict__ Bl, int ldb, long long bB,
    float* Cf, uint16_t* Csh, uint16_t* Csl, int ldc, long long cO, long long cI,
    const float* __restrict__ bias, float scale, int K)
{
    extern __shared__ __align__(16) char smem[];
    const uint32_t sb = smem_u32(smem);
    const int tid = threadIdx.x, lane = tid & 31, wid = tid >> 5;
    const int wm = wid >> 2, wn = wid & 3;
    const int z = blockIdx.z, bm = blockIdx.y, bn = blockIdx.x;

    const uint16_t* pb0 = Ah + (size_t)z * aB + (size_t)bm * 128 * lda;
    const uint16_t* pb1 = Al + (size_t)z * aB + (size_t)bm * 128 * lda;
    const uint16_t* pb2 = Bh + (size_t)z * bB + (size_t)bn * 128 * ldb;
    const uint16_t* pb3 = Bl + (size_t)z * bB + (size_t)bn * 128 * ldb;
    const int nCh = K / 32;

    auto issue = [&](int c) {
        if (c < nCh) {
            const int kc = c * 32;
            const uint32_t sdst = sb + (c & 1) * STG_L;
            const int row = (tid >> 2);           // 0..63
            const int col16 = (tid & 3);          // 16B column
            #pragma unroll
            for (int p = 0; p < 8; p++) {
                const int pl = p >> 1;
                const int r = (p & 1) * 64 + row;
                const uint16_t* src =
                    (pl == 0 ? pb0 : pl == 1 ? pb1 : pl == 2 ? pb2 : pb3);
                const int ld = (pl < 2) ? lda : ldb;
                CP16(sdst + pl * PLA_L + r * PITCH + col16 * 16,
                     src + (size_t)r * ld + kc + col16 * 8);
            }
        }
        CP_COMMIT();
    };

    float acc[4][4][4];
    #pragma unroll
    for (int i = 0; i < 4; i++)
        #pragma unroll
        for (int j = 0; j < 4; j++)
            #pragma unroll
            for (int r = 0; r < 4; r++) acc[i][j][r] = 0.f;

    issue(0); issue(1);

    for (int c = 0; c < nCh; c++) {
        CP_WAIT1();                 // chunk c resident (c+1 may be in flight)
        __syncthreads();

        const uint32_t sbuf = sb + (c & 1) * STG_L;
        #pragma unroll
        for (int k16 = 0; k16 < 2; k16++) {
            uint32_t af[2][4][4];
            uint32_t abase = sbuf + (wm * 64 + (lane & 15)) * PITCH
                           + (k16 * 16 + (lane >> 4) * 8) * 2;
            #pragma unroll
            for (int mt = 0; mt < 4; mt++) {
                ldm4(af[0][mt], abase + mt * 16 * PITCH);
                ldm4(af[1][mt], abase + PLA_L + mt * 16 * PITCH);
            }
            uint32_t bbase = sbuf + 2 * PLA_L
                + (wn * 32 + (lane & 7) + ((lane >> 4) << 3)) * PITCH
                + (k16 * 16 + ((lane >> 3) & 1) * 8) * 2;
            #pragma unroll
            for (int nt2 = 0; nt2 < 2; nt2++) {
                uint32_t bh[4], bl[4];
                ldm4(bh, bbase + nt2 * 16 * PITCH);
                ldm4(bl, bbase + PLA_L + nt2 * 16 * PITCH);
                #pragma unroll
                for (int hf = 0; hf < 2; hf++) {
                    const int nt = nt2 * 2 + hf;
                    #pragma unroll
                    for (int mt = 0; mt < 4; mt++) {
                        mma16816(acc[mt][nt], af[0][mt], &bh[2 * hf]);
                        mma16816(acc[mt][nt], af[0][mt], &bl[2 * hf]);
                        mma16816(acc[mt][nt], af[1][mt], &bh[2 * hf]);
                    }
                }
            }
        }
        __syncthreads();
        issue(c + 2);               // refill the buffer just consumed
    }

    // epilogue
    const long long coff = (long long)(z >> 4) * cO + (long long)(z & 15) * cI;
    #pragma unroll
    for (int nt = 0; nt < 4; nt++) {
        const int gc = bn * 128 + wn * 32 + nt * 8 + (lane & 3) * 2;
        float2 bv = make_float2(0.f, 0.f);
        if (bias) bv = *(const float2*)(bias + gc);
        #pragma unroll
        for (int mt = 0; mt < 4; mt++) {
            const int r0 = bm * 128 + wm * 64 + mt * 16 + (lane >> 2);
            #pragma unroll
            for (int half = 0; half < 2; half++) {
                const long long gp = coff + (long long)(r0 + half * 8) * ldc + gc;
                float v0 = acc[mt][nt][2 * half + 0] * scale + bv.x;
                float v1 = acc[mt][nt][2 * half + 1] * scale + bv.y;
                if (Cf) *(float2*)(Cf + gp) = make_float2(v0, v1);
                if (Csh) {
                    uint2 s = split2(v0, v1);
                    *(uint32_t*)(Csh + gp) = s.x;
                    *(uint32_t*)(Csl + gp) = s.y;
                }
            }
        }
    }
}

__global__ void k_split_x(const float* __restrict__ s, uint16_t* __restrict__ dh,
                          uint16_t* __restrict__ dl, int n2) {
    int i = blockIdx.x * 256 + threadIdx.x;
    if (i < n2) {
        float2 v = *(const float2*)(s + 2 * i);
        uint2 sp = split2(v.x, v.y);
        *(uint32_t*)(dh + 2 * i) = sp.x;
        *(uint32_t*)(dl + 2 * i) = sp.y;
    }
}
__global__ void k_trsp(const float* __restrict__ W, uint16_t* __restrict__ Wth,
                       uint16_t* __restrict__ Wtl, int Kd, int Nd) {
    __shared__ float t[32][33];
    int n0 = blockIdx.x * 32, k0 = blockIdx.y * 32;
    int tx = threadIdx.x, ty = threadIdx.y;
    #pragma unroll
    for (int i = 0; i < 32; i += 8)
        t[ty + i][tx] = W[(size_t)(k0 + ty + i) * Nd + n0 + tx];
    __syncthreads();
    #pragma unroll
    for (int i = 0; i < 32; i += 8) {
        uint16_t h, l; split1(t[tx][ty + i], h, l);
        size_t o = (size_t)(n0 + ty + i) * Kd + k0 + tx;
        Wth[o] = h; Wtl[o] = l;
    }
}
__global__ void k_biascat(const float* a, const float* b, const float* c) {
    int i = blockIdx.x * 256 + threadIdx.x;
    g_bd[i] = (i < 512) ? a[i] : (i < 1024 ? b[i - 512] : c[i - 1024]);
}
__global__ void k_table() {
    int idx = blockIdx.x * 256 + threadIdx.x;
    int s = idx >> 8, i = idx & 255;
    float dv = expf((float)(2 * i) * (-9.210340371976184f / (float)RRx));
    float sn, cs; sincosf((float)s * dv, &sn, &cs);
    g_sin[idx] = sn; g_cos[idx] = cs;
}
__global__ void k_rope_k() {
    int idx = blockIdx.x * 256 + threadIdx.x;
    int i = idx & 255, row = idx >> 8, s = row & (SSx - 1);
    size_t o = (size_t)row * NDOWN + 1024 + 2 * i;
    float vx = join1(g_d0sh[o],     g_d0sl[o]);
    float vy = join1(g_d0sh[o + 1], g_d0sl[o + 1]);
    float sn = g_sin[s * 256 + i], cs = g_cos[s * 256 + i];
    float2 out; out.x = vx * cs - vy * sn; out.y = vy * cs + vx * sn;
    *(float2*)(g_krr + (size_t)row * RRx + 2 * i) = out;
}
__global__ void k_pack_q() {
    int idx = blockIdx.x * 256 + threadIdx.x;
    int p = idx % 320, s = (idx / 320) & (SSx - 1), z = idx / (320 * SSx);
    int b = z >> 4, h = z & 15;
    size_t ro = (size_t)(b * SSx + s);
    size_t base = ((size_t)z * SSx + s) * QKD;
    if (p < 64) {
        float2 v = *(const float2*)(g_qc + ro * UPx + h * VHDx + 2 * p);
        uint2 sp = split2(v.x, v.y);
        *(uint32_t*)(g_qfsh + base + 2 * p) = sp.x;
        *(uint32_t*)(g_qfsl + base + 2 * p) = sp.y;
    } else {
        int i = p - 64;
        float2 v = *(const float2*)(g_qr + ro * (RRx * HHx) + h * RRx + 2 * i);
        float sn = g_sin[s * 256 + i], cs = g_cos[s * 256 + i];
        uint2 sp = split2(v.x * cs - v.y * sn, v.y * cs + v.x * sn);
        *(uint32_t*)(g_qfsh + base + VHDx + 2 * i) = sp.x;
        *(uint32_t*)(g_qfsl + base + VHDx + 2 * i) = sp.y;
    }
}
__global__ void k_pack_k() {
    int idx = blockIdx.x * 256 + threadIdx.x;
    int p = idx % 320, s = (idx / 320) & (SSx - 1), z = idx / (320 * SSx);
    int b = z >> 4, h = z & 15;
    size_t ro = (size_t)(b * SSx + s);
    size_t base = ((size_t)z * SSx + s) * QKD;
    if (p < 64) {
        float2 v = *(const float2*)(g_kc + ro * UPx + h * VHDx + 2 * p);
        uint2 sp = split2(v.x, v.y);
        *(uint32_t*)(g_kfsh + base + 2 * p) = sp.x;
        *(uint32_t*)(g_kfsl + base + 2 * p) = sp.y;
    } else {
        int i = p - 64;
        float2 v = *(const float2*)(g_krr + ro * RRx + 2 * i);
        uint2 sp = split2(v.x, v.y);
        *(uint32_t*)(g_kfsh + base + VHDx + 2 * i) = sp.x;
        *(uint32_t*)(g_kfsl + base + VHDx + 2 * i) = sp.y;
    }
}
__global__ void k_vt() {
    __shared__ float t[32][33];
    int z = blockIdx.z, b = z >> 4, h = z & 15;
    int s0 = blockIdx.x * 32, d0 = blockIdx.y * 32;
    int tx = threadIdx.x, ty = threadIdx.y;
    #pragma unroll
    for (int i = 0; i < 32; i += 8)
        t[ty + i][tx] = g_vc[(size_t)(b * SSx + s0 + ty + i) * UPx + h * VHDx + d0 + tx];
    __syncthreads();
    #pragma unroll
    for (int i = 0; i < 32; i += 8) {
        uint16_t hh, ll; split1(t[tx][ty + i], hh, ll);
        size_t o = (size_t)z * (VHDx * SSx) + (size_t)(d0 + ty + i) * SSx + s0 + tx;
        g_vtsh[o] = hh; g_vtsl[o] = ll;
    }
}
__global__ void __launch_bounds__(128) k_softmax() {
    size_t row = blockIdx.x;
    const float* p = g_sc + row * SSx;
    int t = threadIdx.x;
    float4 v = ((const float4*)p)[t];
    float m = fmaxf(fmaxf(v.x, v.y), fmaxf(v.z, v.w));
    #pragma unroll
    for (int o = 16; o; o >>= 1) m = fmaxf(m, __shfl_xor_sync(0xffffffffu, m, o));
    __shared__ float rm[4], rs[4];
    if ((t & 31) == 0) rm[t >> 5] = m;
    __syncthreads();
    m = fmaxf(fmaxf(rm[0], rm[1]), fmaxf(rm[2], rm[3]));
    v.x = __expf(v.x - m); v.y = __expf(v.y - m);
    v.z = __expf(v.z - m); v.w = __expf(v.w - m);
    float s = v.x + v.y + v.z + v.w;
    #pragma unroll
    for (int o = 16; o; o >>= 1) s += __shfl_xor_sync(0xffffffffu, s, o);
    if ((t & 31) == 0) rs[t >> 5] = s;
    __syncthreads();
    s = rs[0] + rs[1] + rs[2] + rs[3];
    float inv = 1.f / s;
    uint2 s01 = split2(v.x * inv, v.y * inv);
    uint2 s23 = split2(v.z * inv, v.w * inv);
    *(uint2*)(g_psh + row * SSx + t * 4) = make_uint2(s01.x, s23.x);
    *(uint2*)(g_psl + row * SSx + t * 4) = make_uint2(s01.y, s23.y);
}

extern "C" void kernel_launch(void* const* d_in, const int* in_sizes, int n_in,
                              void* d_out, int out_size)
{
    const float* X    = (const float*)d_in[0];
    const float* Wdq  = (const float*)d_in[1];
    const float* bdq  = (const float*)d_in[2];
    const float* Wdkv = (const float*)d_in[3];
    const float* bdkv = (const float*)d_in[4];
    const float* Wuq  = (const float*)d_in[5];
    const float* buq  = (const float*)d_in[6];
    const float* Wuk  = (const float*)d_in[7];
    const float* buk  = (const float*)d_in[8];
    const float* Wuv  = (const float*)d_in[9];
    const float* buv  = (const float*)d_in[10];
    const float* Wqr  = (const float*)d_in[11];
    const float* bqr  = (const float*)d_in[12];
    const float* Wkr  = (const float*)d_in[13];
    const float* bkr  = (const float*)d_in[14];
    const float* Wfc  = (const float*)d_in[15];
    const float* bfc  = (const float*)d_in[16];
    float* out = (float*)d_out;

    cudaFuncSetAttribute(k_gemm, cudaFuncAttributeMaxDynamicSharedMemorySize, SMEMB);

    #define SYM(v, g) void* v; cudaGetSymbolAddress(&v, g)
    SYM(p_xsh, g_xsh);   SYM(p_xsl, g_xsl);
    SYM(p_wdth, g_wdth); SYM(p_wdtl, g_wdtl); SYM(p_bd, g_bd);
    SYM(p_wuqth, g_wuqth); SYM(p_wuqtl, g_wuqtl);
    SYM(p_wukth, g_wukth); SYM(p_wuktl, g_wuktl);
    SYM(p_wuvth, g_wuvth); SYM(p_wuvtl, g_wuvtl);
    SYM(p_wqrth, g_wqrth); SYM(p_wqrtl, g_wqrtl);
    SYM(p_wfcth, g_wfcth); SYM(p_wfctl, g_wfctl);
    SYM(p_d0sh, g_d0sh); SYM(p_d0sl, g_d0sl);
    SYM(p_qc, g_qc); SYM(p_kc, g_kc); SYM(p_vc, g_vc); SYM(p_qr, g_qr);
    SYM(p_qfsh, g_qfsh); SYM(p_qfsl, g_qfsl);
    SYM(p_kfsh, g_kfsh); SYM(p_kfsl, g_kfsl);
    SYM(p_sc, g_sc); SYM(p_psh, g_psh); SYM(p_psl, g_psl);
    SYM(p_vtsh, g_vtsh); SYM(p_vtsl, g_vtsl);
    SYM(p_ofsh, g_ofsh); SYM(p_ofsl, g_ofsl);
    #undef SYM

    dim3 tb(32, 8);
    k_table<<<SSx, 256>>>();
    k_split_x<<<(MROWS * DDx / 2) / 256, 256>>>(X, (uint16_t*)p_xsh, (uint16_t*)p_xsl,
                                                MROWS * DDx / 2);
    k_trsp<<<dim3(16, 64), tb>>>(Wdq,  (uint16_t*)p_wdth, (uint16_t*)p_wdtl, 2048, 512);
    k_trsp<<<dim3(16, 64), tb>>>(Wdkv, (uint16_t*)p_wdth + (size_t)512 * 2048,
                                       (uint16_t*)p_wdtl + (size_t)512 * 2048, 2048, 512);
    k_trsp<<<dim3(16, 64), tb>>>(Wkr,  (uint16_t*)p_wdth + (size_t)1024 * 2048,
                                       (uint16_t*)p_wdtl + (size_t)1024 * 2048, 2048, 512);
    k_trsp<<<dim3(64, 16), tb>>>(Wuq, (uint16_t*)p_wuqth, (uint16_t*)p_wuqtl, 512, 2048);
    k_trsp<<<dim3(64, 16), tb>>>(Wuk, (uint16_t*)p_wukth, (uint16_t*)p_wuktl, 512, 2048);
    k_trsp<<<dim3(64, 16), tb>>>(Wuv, (uint16_t*)p_wuvth, (uint16_t*)p_wuvtl, 512, 2048);
    k_trsp<<<dim3(256, 16), tb>>>(Wqr, (uint16_t*)p_wqrth, (uint16_t*)p_wqrtl, 512, 8192);
    k_trsp<<<dim3(64, 64), tb>>>(Wfc, (uint16_t*)p_wfcth, (uint16_t*)p_wfctl, 2048, 2048);
    k_biascat<<<6, 256>>>(bdq, bdkv, bkr);

    // fused down-proj: M=4096, N=1536, K=2048 (split output only)
    k_gemm<<<dim3(12, 32, 1), 256, SMEMB>>>(
        (uint16_t*)p_xsh, (uint16_t*)p_xsl, DDx, 0,
        (uint16_t*)p_wdth, (uint16_t*)p_wdtl, DDx, 0,
        nullptr, (uint16_t*)p_d0sh, (uint16_t*)p_d0sl, NDOWN, 0, 0,
        (float*)p_bd, 1.f, DDx);
    // up-projections, K=512
    k_gemm<<<dim3(16, 32, 1), 256, SMEMB>>>(
        (uint16_t*)p_d0sh, (uint16_t*)p_d0sl, NDOWN, 0,
        (uint16_t*)p_wuqth, (uint16_t*)p_wuqtl, DWN, 0,
        (float*)p_qc, nullptr, nullptr, UPx, 0, 0, buq, 1.f, DWN);
    k_gemm<<<dim3(64, 32, 1), 256, SMEMB>>>(
        (uint16_t*)p_d0sh, (uint16_t*)p_d0sl, NDOWN, 0,
        (uint16_t*)p_wqrth, (uint16_t*)p_wqrtl, DWN, 0,
        (float*)p_qr, nullptr, nullptr, RRx * HHx, 0, 0, bqr, 1.f, DWN);
    k_gemm<<<dim3(16, 32, 1), 256, SMEMB>>>(
        (uint16_t*)p_d0sh + 512, (uint16_t*)p_d0sl + 512, NDOWN, 0,
        (uint16_t*)p_wukth, (uint16_t*)p_wuktl, DWN, 0,
        (float*)p_kc, nullptr, nullptr, UPx, 0, 0, buk, 1.f, DWN);
    k_gemm<<<dim3(16, 32, 1), 256, SMEMB>>>(
        (uint16_t*)p_d0sh + 512, (uint16_t*)p_d0sl + 512, NDOWN, 0,
        (uint16_t*)p_wuvth, (uint16_t*)p_wuvtl, DWN, 0,
        (float*)p_vc, nullptr, nullptr, UPx, 0, 0, buv, 1.f, DWN);

    k_rope_k<<<MROWS, 256>>>();
    k_pack_q<<<(ZBx * SSx * 320) / 256, 256>>>();
    k_pack_k<<<(ZBx * SSx * 320) / 256, 256>>>();
    k_vt<<<dim3(16, 4, ZBx), tb>>>();

    // scores: per z M=512, N=512, K=640
    k_gemm<<<dim3(4, 4, ZBx), 256, SMEMB>>>(
        (uint16_t*)p_qfsh, (uint16_t*)p_qfsl, QKD, (long long)SSx * QKD,
        (uint16_t*)p_kfsh, (uint16_t*)p_kfsl, QKD, (long long)SSx * QKD,
        (float*)p_sc, nullptr, nullptr, SSx,
        (long long)16 * SSx * SSx, (long long)SSx * SSx,
        nullptr, INV_SCALE, QKD);

    k_softmax<<<ZBx * SSx, 128>>>();

    // PV: per z M=512, N=128, K=512 -> split store scattered to [b,s,h*128+d]
    k_gemm<<<dim3(1, 4, ZBx), 256, SMEMB>>>(
        (uint16_t*)p_psh, (uint16_t*)p_psl, SSx, (long long)SSx * SSx,
        (uint16_t*)p_vtsh, (uint16_t*)p_vtsl, SSx, (long long)VHDx * SSx,
        nullptr, (uint16_t*)p_ofsh, (uint16_t*)p_ofsl, UPx,
        (long long)SSx * UPx, (long long)VHDx,
        nullptr, 1.f, SSx);

    // final: M=4096, N=2048, K=2048 -> out fp32
    k_gemm<<<dim3(16, 32, 1), 256, SMEMB>>>(
        (uint16_t*)p_ofsh, (uint16_t*)p_ofsl, UPx, 0,
        (uint16_t*)p_wfcth, (uint16_t*)p_wfctl, DDx, 0,
        out, nullptr, nullptr, DDx, 0, 0, bfc, 1.f, DDx);
}

// round 7
// speedup vs baseline: 2.8593x; 1.0420x over previous
#include <cuda_runtime.h>
#include <cuda_bf16.h>
#include <cstdint>
#include <math.h>

#define BBx   8
#define SSx   512
#define DDx   2048
#define HHx   16
#define DWN   512
#define UPx   2048
#define RRx   512
#define VHDx  128
#define MROWS (BBx*SSx)
#define ZBx   (BBx*HHx)
#define QKD   (VHDx+RRx)
#define NDOWN (DWN*3)
#define NQ    (UPx + RRx*HHx)     // 10240  (qc | qr)
#define NKV   (UPx + UPx)         // 4096   (kc | vc)
#define INV_SCALE 0.0294627825494394758f

// hi/lo bf16 planes stored separately (pure-copy staging for cp.async)
__device__ uint16_t g_xsh [(size_t)MROWS*DDx];
__device__ uint16_t g_xsl [(size_t)MROWS*DDx];
__device__ uint16_t g_wdth[(size_t)NDOWN*DDx];
__device__ uint16_t g_wdtl[(size_t)NDOWN*DDx];
__device__ float    g_bd  [NDOWN];
__device__ uint16_t g_wqth[(size_t)NQ*DWN];     // [Wuq^T ; Wqr^T]
__device__ uint16_t g_wqtl[(size_t)NQ*DWN];
__device__ uint16_t g_wkvth[(size_t)NKV*DWN];   // [Wuk^T ; Wuv^T]
__device__ uint16_t g_wkvtl[(size_t)NKV*DWN];
__device__ float    g_bq  [NQ];
__device__ float    g_bkv [NKV];
__device__ uint16_t g_wfcth[(size_t)DDx*DDx];
__device__ uint16_t g_wfctl[(size_t)DDx*DDx];
__device__ uint16_t g_d0sh[(size_t)MROWS*NDOWN];
__device__ uint16_t g_d0sl[(size_t)MROWS*NDOWN];
__device__ float    g_qcf [(size_t)MROWS*NQ];   // [qc | qr]
__device__ float    g_kvf [(size_t)MROWS*NKV];  // [kc | vc]
__device__ float    g_krr [(size_t)MROWS*RRx];
__device__ uint16_t g_qfsh[(size_t)ZBx*SSx*QKD];
__device__ uint16_t g_qfsl[(size_t)ZBx*SSx*QKD];
__device__ uint16_t g_kfsh[(size_t)ZBx*SSx*QKD];
__device__ uint16_t g_kfsl[(size_t)ZBx*SSx*QKD];
__device__ float    g_sc  [(size_t)ZBx*SSx*SSx];
__device__ uint16_t g_psh [(size_t)ZBx*SSx*SSx];
__device__ uint16_t g_psl [(size_t)ZBx*SSx*SSx];
__device__ uint16_t g_vtsh[(size_t)ZBx*VHDx*SSx];
__device__ uint16_t g_vtsl[(size_t)ZBx*VHDx*SSx];
__device__ uint16_t g_ofsh[(size_t)MROWS*UPx];
__device__ uint16_t g_ofsl[(size_t)MROWS*UPx];
__device__ float    g_sin [SSx*(RRx/2)];
__device__ float    g_cos [SSx*(RRx/2)];

__device__ __forceinline__ uint32_t smem_u32(const void* p) {
    uint32_t a;
    asm("{ .reg .u64 t; cvta.to.shared.u64 t, %1; cvt.u32.u64 %0, t; }" : "=r"(a) : "l"(p));
    return a;
}
__device__ __forceinline__ void split1(float v, uint16_t& h, uint16_t& l) {
    __nv_bfloat16 hb = __float2bfloat16(v);
    __nv_bfloat16 lb = __float2bfloat16(v - __bfloat162float(hb));
    h = __bfloat16_as_ushort(hb); l = __bfloat16_as_ushort(lb);
}
__device__ __forceinline__ uint2 split2(float a, float b) {
    uint16_t ah, al, bh, bl; split1(a, ah, al); split1(b, bh, bl);
    return make_uint2((uint32_t)ah | ((uint32_t)bh << 16),
                      (uint32_t)al | ((uint32_t)bl << 16));
}
__device__ __forceinline__ float join1(uint16_t h, uint16_t l) {
    return __bfloat162float(__ushort_as_bfloat16(h)) +
           __bfloat162float(__ushort_as_bfloat16(l));
}
__device__ __forceinline__ void ldm4(uint32_t* r, uint32_t addr) {
    asm volatile("ldmatrix.sync.aligned.m8n8.x4.shared.b16 {%0,%1,%2,%3}, [%4];"
        : "=r"(r[0]), "=r"(r[1]), "=r"(r[2]), "=r"(r[3]) : "r"(addr));
}
__device__ __forceinline__ void mma16816(float* c, const uint32_t* a, const uint32_t* b) {
    asm volatile("mma.sync.aligned.m16n8k16.row.col.f32.bf16.bf16.f32 "
        "{%0,%1,%2,%3}, {%4,%5,%6,%7}, {%8,%9}, {%0,%1,%2,%3};"
        : "+f"(c[0]), "+f"(c[1]), "+f"(c[2]), "+f"(c[3])
        : "r"(a[0]), "r"(a[1]), "r"(a[2]), "r"(a[3]), "r"(b[0]), "r"(b[1]));
}
#define CP16(dst, src) \
    asm volatile("cp.async.cg.shared.global [%0], [%1], 16;" :: "r"(dst), "l"(src))
#define CP_COMMIT() asm volatile("cp.async.commit_group;" ::: "memory")
#define CP_WAIT0()  asm volatile("cp.async.wait_group 0;" ::: "memory")

// smem plane: 128 rows x 80B pitch (64B payload = 32 bf16). Planes: Ah, Al, Bh, Bl.
#define PITCH  80
#define PLA_L  (128*PITCH)
#define STG_L  (4*PLA_L)          // 40960 per stage
#define SMEMB  (2*STG_L)          // 81920 -> 2 CTAs/SM

// C = scale*(A @ B^T) + bias.  A,B given as hi/lo bf16 planes. BM=BN=128, BK=32.
__global__ void __launch_bounds__(256, 2) k_gemm(
    const uint16_t* __restrict__ Ah, const uint16_t* __restrict__ Al, int lda, long long aB,
    const uint16_t* __restrict__ Bh, const uint16_t* __restrict__ Bl, int ldb, long long bB,
    float* Cf, uint16_t* Csh, uint16_t* Csl, int ldc, long long cO, long long cI,
    const float* __restrict__ bias, float scale, int K)
{
    extern __shared__ __align__(16) char smem[];
    const uint32_t sb = smem_u32(smem);
    const int tid = threadIdx.x, lane = tid & 31, wid = tid >> 5;
    const int wm = wid >> 2, wn = wid & 3;
    const int z = blockIdx.z, bm = blockIdx.y, bn = blockIdx.x;

    const uint16_t* pb0 = Ah + (size_t)z * aB + (size_t)bm * 128 * lda;
    const uint16_t* pb1 = Al + (size_t)z * aB + (size_t)bm * 128 * lda;
    const uint16_t* pb2 = Bh + (size_t)z * bB + (size_t)bn * 128 * ldb;
    const uint16_t* pb3 = Bl + (size_t)z * bB + (size_t)bn * 128 * ldb;
    const int nCh = K / 32;

    auto issue = [&](int c) {
        if (c < nCh) {
            const int kc = c * 32;
            const uint32_t sdst = sb + (c & 1) * STG_L;
            const int row = (tid >> 2);           // 0..63
            const int col16 = (tid & 3);          // 16B column
            #pragma unroll
            for (int p = 0; p < 8; p++) {
                const int pl = p >> 1;
                const int r = (p & 1) * 64 + row;
                const uint16_t* src =
                    (pl == 0 ? pb0 : pl == 1 ? pb1 : pl == 2 ? pb2 : pb3);
                const int ld = (pl < 2) ? lda : ldb;
                CP16(sdst + pl * PLA_L + r * PITCH + col16 * 16,
                     src + (size_t)r * ld + kc + col16 * 8);
            }
            CP_COMMIT();
        }
    };

    float acc[4][4][4];
    #pragma unroll
    for (int i = 0; i < 4; i++)
        #pragma unroll
        for (int j = 0; j < 4; j++)
            #pragma unroll
            for (int r = 0; r < 4; r++) acc[i][j][r] = 0.f;

    issue(0);

    for (int c = 0; c < nCh; c++) {
        CP_WAIT0();                 // only copy(c) is outstanding here
        __syncthreads();            // publishes copy(c); proves compute(c-1) done
        issue(c + 1);               // refill other buffer; overlaps compute(c)

        const uint32_t sbuf = sb + (c & 1) * STG_L;
        #pragma unroll
        for (int k16 = 0; k16 < 2; k16++) {
            uint32_t af[2][4][4];
            uint32_t abase = sbuf + (wm * 64 + (lane & 15)) * PITCH
                           + (k16 * 16 + (lane >> 4) * 8) * 2;
            #pragma unroll
            for (int mt = 0; mt < 4; mt++) {
                ldm4(af[0][mt], abase + mt * 16 * PITCH);
                ldm4(af[1][mt], abase + PLA_L + mt * 16 * PITCH);
            }
            uint32_t bbase = sbuf + 2 * PLA_L
                + (wn * 32 + (lane & 7) + ((lane >> 4) << 3)) * PITCH
                + (k16 * 16 + ((lane >> 3) & 1) * 8) * 2;
            #pragma unroll
            for (int nt2 = 0; nt2 < 2; nt2++) {
                uint32_t bh[4], bl[4];
                ldm4(bh, bbase + nt2 * 16 * PITCH);
                ldm4(bl, bbase + PLA_L + nt2 * 16 * PITCH);
                #pragma unroll
                for (int hf = 0; hf < 2; hf++) {
                    const int nt = nt2 * 2 + hf;
                    #pragma unroll
                    for (int mt = 0; mt < 4; mt++) {
                        mma16816(acc[mt][nt], af[0][mt], &bh[2 * hf]);
                        mma16816(acc[mt][nt], af[0][mt], &bl[2 * hf]);
                        mma16816(acc[mt][nt], af[1][mt], &bh[2 * hf]);
                    }
                }
            }
        }
    }

    // epilogue
    const long long coff = (long long)(z >> 4) * cO + (long long)(z & 15) * cI;
    #pragma unroll
    for (int nt = 0; nt < 4; nt++) {
        const int gc = bn * 128 + wn * 32 + nt * 8 + (lane & 3) * 2;
        float2 bv = make_float2(0.f, 0.f);
        if (bias) bv = *(const float2*)(bias + gc);
        #pragma unroll
        for (int mt = 0; mt < 4; mt++) {
            const int r0 = bm * 128 + wm * 64 + mt * 16 + (lane >> 2);
            #pragma unroll
            for (int half = 0; half < 2; half++) {
                const long long gp = coff + (long long)(r0 + half * 8) * ldc + gc;
                float v0 = acc[mt][nt][2 * half + 0] * scale + bv.x;
                float v1 = acc[mt][nt][2 * half + 1] * scale + bv.y;
                if (Cf) *(float2*)(Cf + gp) = make_float2(v0, v1);
                if (Csh) {
                    uint2 s = split2(v0, v1);
                    *(uint32_t*)(Csh + gp) = s.x;
                    *(uint32_t*)(Csl + gp) = s.y;
                }
            }
        }
    }
}

__global__ void k_split_x(const float* __restrict__ s, uint16_t* __restrict__ dh,
                          uint16_t* __restrict__ dl, int n2) {
    int i = blockIdx.x * 256 + threadIdx.x;
    if (i < n2) {
        float2 v = *(const float2*)(s + 2 * i);
        uint2 sp = split2(v.x, v.y);
        *(uint32_t*)(dh + 2 * i) = sp.x;
        *(uint32_t*)(dl + 2 * i) = sp.y;
    }
}
__global__ void k_trsp(const float* __restrict__ W, uint16_t* __restrict__ Wth,
                       uint16_t* __restrict__ Wtl, int Kd, int Nd) {
    __shared__ float t[32][33];
    int n0 = blockIdx.x * 32, k0 = blockIdx.y * 32;
    int tx = threadIdx.x, ty = threadIdx.y;
    #pragma unroll
    for (int i = 0; i < 32; i += 8)
        t[ty + i][tx] = W[(size_t)(k0 + ty + i) * Nd + n0 + tx];
    __syncthreads();
    #pragma unroll
    for (int i = 0; i < 32; i += 8) {
        uint16_t h, l; split1(t[tx][ty + i], h, l);
        size_t o = (size_t)(n0 + ty + i) * Kd + k0 + tx;
        Wth[o] = h; Wtl[o] = l;
    }
}
__global__ void k_cat3(float* dst, const float* a, const float* b, const float* c,
                       int na, int nb, int nc) {
    int i = blockIdx.x * 256 + threadIdx.x;
    if (i < na) dst[i] = a[i];
    else if (i < na + nb) dst[i] = b[i - na];
    else if (i < na + nb + nc) dst[i] = c[i - na - nb];
}
__global__ void k_cat2(float* dst, const float* a, const float* b, int na, int nb) {
    int i = blockIdx.x * 256 + threadIdx.x;
    if (i < na) dst[i] = a[i];
    else if (i < na + nb) dst[i] = b[i - na];
}
__global__ void k_table() {
    int idx = blockIdx.x * 256 + threadIdx.x;
    int s = idx >> 8, i = idx & 255;
    float dv = expf((float)(2 * i) * (-9.210340371976184f / (float)RRx));
    float sn, cs; sincosf((float)s * dv, &sn, &cs);
    g_sin[idx] = sn; g_cos[idx] = cs;
}
__global__ void k_rope_k() {
    int idx = blockIdx.x * 256 + threadIdx.x;
    int i = idx & 255, row = idx >> 8, s = row & (SSx - 1);
    size_t o = (size_t)row * NDOWN + 1024 + 2 * i;
    float vx = join1(g_d0sh[o],     g_d0sl[o]);
    float vy = join1(g_d0sh[o + 1], g_d0sl[o + 1]);
    float sn = g_sin[s * 256 + i], cs = g_cos[s * 256 + i];
    float2 out; out.x = vx * cs - vy * sn; out.y = vy * cs + vx * sn;
    *(float2*)(g_krr + (size_t)row * RRx + 2 * i) = out;
}
__global__ void k_pack_q() {
    int idx = blockIdx.x * 256 + threadIdx.x;
    int p = idx % 320, s = (idx / 320) & (SSx - 1), z = idx / (320 * SSx);
    int b = z >> 4, h = z & 15;
    size_t ro = (size_t)(b * SSx + s);
    size_t base = ((size_t)z * SSx + s) * QKD;
    if (p < 64) {
        float2 v = *(const float2*)(g_qcf + ro * NQ + h * VHDx + 2 * p);
        uint2 sp = split2(v.x, v.y);
        *(uint32_t*)(g_qfsh + base + 2 * p) = sp.x;
        *(uint32_t*)(g_qfsl + base + 2 * p) = sp.y;
    } else {
        int i = p - 64;
        float2 v = *(const float2*)(g_qcf + ro * NQ + UPx + h * RRx + 2 * i);
        float sn = g_sin[s * 256 + i], cs = g_cos[s * 256 + i];
        uint2 sp = split2(v.x * cs - v.y * sn, v.y * cs + v.x * sn);
        *(uint32_t*)(g_qfsh + base + VHDx + 2 * i) = sp.x;
        *(uint32_t*)(g_qfsl + base + VHDx + 2 * i) = sp.y;
    }
}
__global__ void k_pack_k() {
    int idx = blockIdx.x * 256 + threadIdx.x;
    int p = idx % 320, s = (idx / 320) & (SSx - 1), z = idx / (320 * SSx);
    int b = z >> 4, h = z & 15;
    size_t ro = (size_t)(b * SSx + s);
    size_t base = ((size_t)z * SSx + s) * QKD;
    if (p < 64) {
        float2 v = *(const float2*)(g_kvf + ro * NKV + h * VHDx + 2 * p);
        uint2 sp = split2(v.x, v.y);
        *(uint32_t*)(g_kfsh + base + 2 * p) = sp.x;
        *(uint32_t*)(g_kfsl + base + 2 * p) = sp.y;
    } else {
        int i = p - 64;
        float2 v = *(const float2*)(g_krr + ro * RRx + 2 * i);
        uint2 sp = split2(v.x, v.y);
        *(uint32_t*)(g_kfsh + base + VHDx + 2 * i) = sp.x;
        *(uint32_t*)(g_kfsl + base + VHDx + 2 * i) = sp.y;
    }
}
__global__ void k_vt() {
    __shared__ float t[32][33];
    int z = blockIdx.z, b = z >> 4, h = z & 15;
    int s0 = blockIdx.x * 32, d0 = blockIdx.y * 32;
    int tx = threadIdx.x, ty = threadIdx.y;
    #pragma unroll
    for (int i = 0; i < 32; i += 8)
        t[ty + i][tx] = g_kvf[(size_t)(b * SSx + s0 + ty + i) * NKV + UPx + h * VHDx + d0 + tx];
    __syncthreads();
    #pragma unroll
    for (int i = 0; i < 32; i += 8) {
        uint16_t hh, ll; split1(t[tx][ty + i], hh, ll);
        size_t o = (size_t)z * (VHDx * SSx) + (size_t)(d0 + ty + i) * SSx + s0 + tx;
        g_vtsh[o] = hh; g_vtsl[o] = ll;
    }
}
__global__ void __launch_bounds__(128) k_softmax() {
    size_t row = blockIdx.x;
    const float* p = g_sc + row * SSx;
    int t = threadIdx.x;
    float4 v = ((const float4*)p)[t];
    float m = fmaxf(fmaxf(v.x, v.y), fmaxf(v.z, v.w));
    #pragma unroll
    for (int o = 16; o; o >>= 1) m = fmaxf(m, __shfl_xor_sync(0xffffffffu, m, o));
    __shared__ float rm[4], rs[4];
    if ((t & 31) == 0) rm[t >> 5] = m;
    __syncthreads();
    m = fmaxf(fmaxf(rm[0], rm[1]), fmaxf(rm[2], rm[3]));
    v.x = __expf(v.x - m); v.y = __expf(v.y - m);
    v.z = __expf(v.z - m); v.w = __expf(v.w - m);
    float s = v.x + v.y + v.z + v.w;
    #pragma unroll
    for (int o = 16; o; o >>= 1) s += __shfl_xor_sync(0xffffffffu, s, o);
    if ((t & 31) == 0) rs[t >> 5] = s;
    __syncthreads();
    s = rs[0] + rs[1] + rs[2] + rs[3];
    float inv = 1.f / s;
    uint2 s01 = split2(v.x * inv, v.y * inv);
    uint2 s23 = split2(v.z * inv, v.w * inv);
    *(uint2*)(g_psh + row * SSx + t * 4) = make_uint2(s01.x, s23.x);
    *(uint2*)(g_psl + row * SSx + t * 4) = make_uint2(s01.y, s23.y);
}

extern "C" void kernel_launch(void* const* d_in, const int* in_sizes, int n_in,
                              void* d_out, int out_size)
{
    const float* X    = (const float*)d_in[0];
    const float* Wdq  = (const float*)d_in[1];
    const float* bdq  = (const float*)d_in[2];
    const float* Wdkv = (const float*)d_in[3];
    const float* bdkv = (const float*)d_in[4];
    const float* Wuq  = (const float*)d_in[5];
    const float* buq  = (const float*)d_in[6];
    const float* Wuk  = (const float*)d_in[7];
    const float* buk  = (const float*)d_in[8];
    const float* Wuv  = (const float*)d_in[9];
    const float* buv  = (const float*)d_in[10];
    const float* Wqr  = (const float*)d_in[11];
    const float* bqr  = (const float*)d_in[12];
    const float* Wkr  = (const float*)d_in[13];
    const float* bkr  = (const float*)d_in[14];
    const float* Wfc  = (const float*)d_in[15];
    const float* bfc  = (const float*)d_in[16];
    float* out = (float*)d_out;

    cudaFuncSetAttribute(k_gemm, cudaFuncAttributeMaxDynamicSharedMemorySize, SMEMB);

    #define SYM(v, g) void* v; cudaGetSymbolAddress(&v, g)
    SYM(p_xsh, g_xsh);   SYM(p_xsl, g_xsl);
    SYM(p_wdth, g_wdth); SYM(p_wdtl, g_wdtl); SYM(p_bd, g_bd);
    SYM(p_wqth, g_wqth); SYM(p_wqtl, g_wqtl);
    SYM(p_wkvth, g_wkvth); SYM(p_wkvtl, g_wkvtl);
    SYM(p_bq, g_bq); SYM(p_bkv, g_bkv);
    SYM(p_wfcth, g_wfcth); SYM(p_wfctl, g_wfctl);
    SYM(p_d0sh, g_d0sh); SYM(p_d0sl, g_d0sl);
    SYM(p_qcf, g_qcf); SYM(p_kvf, g_kvf);
    SYM(p_qfsh, g_qfsh); SYM(p_qfsl, g_qfsl);
    SYM(p_kfsh, g_kfsh); SYM(p_kfsl, g_kfsl);
    SYM(p_sc, g_sc); SYM(p_psh, g_psh); SYM(p_psl, g_psl);
    SYM(p_vtsh, g_vtsh); SYM(p_vtsl, g_vtsl);
    SYM(p_ofsh, g_ofsh); SYM(p_ofsl, g_ofsl);
    #undef SYM

    dim3 tb(32, 8);
    k_table<<<SSx, 256>>>();
    k_split_x<<<(MROWS * DDx / 2) / 256, 256>>>(X, (uint16_t*)p_xsh, (uint16_t*)p_xsl,
                                                MROWS * DDx / 2);
    // down-proj weights: [Wdq | Wdkv | Wkr]^T  (rows = N, cols = K=2048)
    k_trsp<<<dim3(16, 64), tb>>>(Wdq,  (uint16_t*)p_wdth, (uint16_t*)p_wdtl, 2048, 512);
    k_trsp<<<dim3(16, 64), tb>>>(Wdkv, (uint16_t*)p_wdth + (size_t)512 * 2048,
                                       (uint16_t*)p_wdtl + (size_t)512 * 2048, 2048, 512);
    k_trsp<<<dim3(16, 64), tb>>>(Wkr,  (uint16_t*)p_wdth + (size_t)1024 * 2048,
                                       (uint16_t*)p_wdtl + (size_t)1024 * 2048, 2048, 512);
    // q-side weights: [Wuq | Wqr]^T  (N=10240, K=512)
    k_trsp<<<dim3(64, 16), tb>>>(Wuq, (uint16_t*)p_wqth, (uint16_t*)p_wqtl, 512, 2048);
    k_trsp<<<dim3(256, 16), tb>>>(Wqr, (uint16_t*)p_wqth + (size_t)UPx * 512,
                                       (uint16_t*)p_wqtl + (size_t)UPx * 512, 512, 8192);
    // kv-side weights: [Wuk | Wuv]^T (N=4096, K=512)
    k_trsp<<<dim3(64, 16), tb>>>(Wuk, (uint16_t*)p_wkvth, (uint16_t*)p_wkvtl, 512, 2048);
    k_trsp<<<dim3(64, 16), tb>>>(Wuv, (uint16_t*)p_wkvth + (size_t)UPx * 512,
                                      (uint16_t*)p_wkvtl + (size_t)UPx * 512, 512, 2048);
    k_trsp<<<dim3(64, 64), tb>>>(Wfc, (uint16_t*)p_wfcth, (uint16_t*)p_wfctl, 2048, 2048);
    k_cat3<<<(NDOWN + 255) / 256, 256>>>((float*)p_bd, bdq, bdkv, bkr, 512, 512, 512);
    k_cat2<<<(NQ + 255) / 256, 256>>>((float*)p_bq, buq, bqr, UPx, RRx * HHx);
    k_cat2<<<(NKV + 255) / 256, 256>>>((float*)p_bkv, buk, buv, UPx, UPx);

    // fused down-proj: M=4096, N=1536, K=2048 (split output only)
    k_gemm<<<dim3(12, 32, 1), 256, SMEMB>>>(
        (uint16_t*)p_xsh, (uint16_t*)p_xsl, DDx, 0,
        (uint16_t*)p_wdth, (uint16_t*)p_wdtl, DDx, 0,
        nullptr, (uint16_t*)p_d0sh, (uint16_t*)p_d0sl, NDOWN, 0, 0,
        (float*)p_bd, 1.f, DDx);

    // merged q-side up-proj: M=4096, N=10240, K=512
    k_gemm<<<dim3(80, 32, 1), 256, SMEMB>>>(
        (uint16_t*)p_d0sh, (uint16_t*)p_d0sl, NDOWN, 0,
        (uint16_t*)p_wqth, (uint16_t*)p_wqtl, DWN, 0,
        (float*)p_qcf, nullptr, nullptr, NQ, 0, 0, (float*)p_bq, 1.f, DWN);
    // merged kv-side up-proj: M=4096, N=4096, K=512
    k_gemm<<<dim3(32, 32, 1), 256, SMEMB>>>(
        (uint16_t*)p_d0sh + 512, (uint16_t*)p_d0sl + 512, NDOWN, 0,
        (uint16_t*)p_wkvth, (uint16_t*)p_wkvtl, DWN, 0,
        (float*)p_kvf, nullptr, nullptr, NKV, 0, 0, (float*)p_bkv, 1.f, DWN);

    k_rope_k<<<MROWS, 256>>>();
    k_pack_q<<<(ZBx * SSx * 320) / 256, 256>>>();
    k_pack_k<<<(ZBx * SSx * 320) / 256, 256>>>();
    k_vt<<<dim3(16, 4, ZBx), tb>>>();

    // scores: per z M=512, N=512, K=640
    k_gemm<<<dim3(4, 4, ZBx), 256, SMEMB>>>(
        (uint16_t*)p_qfsh, (uint16_t*)p_qfsl, QKD, (long long)SSx * QKD,
        (uint16_t*)p_kfsh, (uint16_t*)p_kfsl, QKD, (long long)SSx * QKD,
        (float*)p_sc, nullptr, nullptr, SSx,
        (long long)16 * SSx * SSx, (long long)SSx * SSx,
        nullptr, INV_SCALE, QKD);

    k_softmax<<<ZBx * SSx, 128>>>();

    // PV: per z M=512, N=128, K=512 -> split store scattered to [b,s,h*128+d]
    k_gemm<<<dim3(1, 4, ZBx), 256, SMEMB>>>(
        (uint16_t*)p_psh, (uint16_t*)p_psl, SSx, (long long)SSx * SSx,
        (uint16_t*)p_vtsh, (uint16_t*)p_vtsl, SSx, (long long)VHDx * SSx,
        nullptr, (uint16_t*)p_ofsh, (uint16_t*)p_ofsl, UPx,
        (long long)SSx * UPx, (long long)VHDx,
        nullptr, 1.f, SSx);

    // final: M=4096, N=2048, K=2048 -> out fp32
    k_gemm<<<dim3(16, 32, 1), 256, SMEMB>>>(
        (uint16_t*)p_ofsh, (uint16_t*)p_ofsl, UPx, 0,
        (uint16_t*)p_wfcth, (uint16_t*)p_wfctl, DDx, 0,
        out, nullptr, nullptr, DDx, 0, 0, bfc, 1.f, DDx);
}

// round 8
// speedup vs baseline: 3.7877x; 1.3247x over previous
#include <cuda_runtime.h>
#include <cuda_fp16.h>
#include <cstdint>
#include <math.h>

#define BBx   8
#define SSx   512
#define DDx   2048
#define HHx   16
#define DWN   512
#define UPx   2048
#define RRx   512
#define VHDx  128
#define MROWS (BBx*SSx)
#define ZBx   (BBx*HHx)
#define QKD   (VHDx+RRx)
#define NDOWN (DWN*3)
#define NQ    (UPx + RRx*HHx)     // 10240  (qc | qr)
#define NKV   (UPx + UPx)         // 4096   (kc | vc)
#define INV_SCALE 0.0294627825494394758f

// A-side tensors: fp16 hi+lo planes (exact). B-side tensors: single fp16 plane.
__device__ uint16_t g_xsh [(size_t)MROWS*DDx];
__device__ uint16_t g_xsl [(size_t)MROWS*DDx];
__device__ uint16_t g_wdth[(size_t)NDOWN*DDx];      // B
__device__ float    g_bd  [NDOWN];
__device__ uint16_t g_wqth[(size_t)NQ*DWN];         // B
__device__ uint16_t g_wkvth[(size_t)NKV*DWN];       // B
__device__ float    g_bq  [NQ];
__device__ float    g_bkv [NKV];
__device__ uint16_t g_wfcth[(size_t)DDx*DDx];       // B
__device__ uint16_t g_d0sh[(size_t)MROWS*NDOWN];
__device__ uint16_t g_d0sl[(size_t)MROWS*NDOWN];
__device__ float    g_qcf [(size_t)MROWS*NQ];
__device__ float    g_kvf [(size_t)MROWS*NKV];
__device__ float    g_krr [(size_t)MROWS*RRx];
__device__ uint16_t g_qfsh[(size_t)ZBx*SSx*QKD];
__device__ uint16_t g_qfsl[(size_t)ZBx*SSx*QKD];
__device__ uint16_t g_kfsh[(size_t)ZBx*SSx*QKD];    // B
__device__ float    g_sc  [(size_t)ZBx*SSx*SSx];
__device__ uint16_t g_psh [(size_t)ZBx*SSx*SSx];
__device__ uint16_t g_psl [(size_t)ZBx*SSx*SSx];
__device__ uint16_t g_vtsh[(size_t)ZBx*VHDx*SSx];   // B
__device__ uint16_t g_ofsh[(size_t)MROWS*UPx];
__device__ uint16_t g_ofsl[(size_t)MROWS*UPx];
__device__ float    g_sin [SSx*(RRx/2)];
__device__ float    g_cos [SSx*(RRx/2)];

__device__ __forceinline__ uint32_t smem_u32(const void* p) {
    uint32_t a;
    asm("{ .reg .u64 t; cvta.to.shared.u64 t, %1; cvt.u32.u64 %0, t; }" : "=r"(a) : "l"(p));
    return a;
}
__device__ __forceinline__ void split1(float v, uint16_t& h, uint16_t& l) {
    __half hb = __float2half_rn(v);
    __half lb = __float2half_rn(v - __half2float(hb));
    h = __half_as_ushort(hb); l = __half_as_ushort(lb);
}
__device__ __forceinline__ uint2 split2(float a, float b) {
    uint16_t ah, al, bh, bl; split1(a, ah, al); split1(b, bh, bl);
    return make_uint2((uint32_t)ah | ((uint32_t)bh << 16),
                      (uint32_t)al | ((uint32_t)bl << 16));
}
__device__ __forceinline__ uint32_t h2pack(float a, float b) {
    __half2 h = __floats2half2_rn(a, b);
    return *(uint32_t*)&h;
}
__device__ __forceinline__ float join1(uint16_t h, uint16_t l) {
    return __half2float(__ushort_as_half(h)) + __half2float(__ushort_as_half(l));
}
__device__ __forceinline__ void ldm4(uint32_t* r, uint32_t addr) {
    asm volatile("ldmatrix.sync.aligned.m8n8.x4.shared.b16 {%0,%1,%2,%3}, [%4];"
        : "=r"(r[0]), "=r"(r[1]), "=r"(r[2]), "=r"(r[3]) : "r"(addr));
}
__device__ __forceinline__ void mma16816(float* c, const uint32_t* a, const uint32_t* b) {
    asm volatile("mma.sync.aligned.m16n8k16.row.col.f32.f16.f16.f32 "
        "{%0,%1,%2,%3}, {%4,%5,%6,%7}, {%8,%9}, {%0,%1,%2,%3};"
        : "+f"(c[0]), "+f"(c[1]), "+f"(c[2]), "+f"(c[3])
        : "r"(a[0]), "r"(a[1]), "r"(a[2]), "r"(a[3]), "r"(b[0]), "r"(b[1]));
}
#define CP16(dst, src) \
    asm volatile("cp.async.cg.shared.global [%0], [%1], 16;" :: "r"(dst), "l"(src))
#define CP_COMMIT() asm volatile("cp.async.commit_group;" ::: "memory")
#define CP_WAIT0()  asm volatile("cp.async.wait_group 0;" ::: "memory")

// smem plane: 128 rows x 80B pitch (64B payload = 32 fp16). Planes: Ah, Al, Bh.
#define PITCH  80
#define PLA_L  (128*PITCH)
#define STG_L  (3*PLA_L)          // 30720 per stage
#define SMEMB  (2*STG_L)          // 61440 -> 2 CTAs/SM

// C = scale*(A @ B^T) + bias.  A: fp16 hi+lo planes (exact); B: fp16. BM=BN=128, BK=32.
__global__ void __launch_bounds__(256, 2) k_gemm(
    const uint16_t* __restrict__ Ah, const uint16_t* __restrict__ Al, int lda, long long aB,
    const uint16_t* __restrict__ Bh, int ldb, long long bB,
    float* Cf, uint16_t* Csh, uint16_t* Csl, int ldc, long long cO, long long cI,
    const float* __restrict__ bias, float scale, int K)
{
    extern __shared__ __align__(16) char smem[];
    const uint32_t sb = smem_u32(smem);
    const int tid = threadIdx.x, lane = tid & 31, wid = tid >> 5;
    const int wm = wid >> 2, wn = wid & 3;
    const int z = blockIdx.z, bm = blockIdx.y, bn = blockIdx.x;

    const uint16_t* pb0 = Ah + (size_t)z * aB + (size_t)bm * 128 * lda;
    const uint16_t* pb1 = Al + (size_t)z * aB + (size_t)bm * 128 * lda;
    const uint16_t* pb2 = Bh + (size_t)z * bB + (size_t)bn * 128 * ldb;
    const int nCh = K / 32;

    auto issue = [&](int c) {
        if (c < nCh) {
            const int kc = c * 32;
            const uint32_t sdst = sb + (c & 1) * STG_L;
            const int row = (tid >> 2);           // 0..63
            const int col16 = (tid & 3);          // 16B column
            #pragma unroll
            for (int p = 0; p < 6; p++) {
                const int pl = p >> 1;
                const int r = (p & 1) * 64 + row;
                const uint16_t* src = (pl == 0 ? pb0 : pl == 1 ? pb1 : pb2);
                const int ld = (pl < 2) ? lda : ldb;
                CP16(sdst + pl * PLA_L + r * PITCH + col16 * 16,
                     src + (size_t)r * ld + kc + col16 * 8);
            }
            CP_COMMIT();
        }
    };

    float acc[4][4][4];
    #pragma unroll
    for (int i = 0; i < 4; i++)
        #pragma unroll
        for (int j = 0; j < 4; j++)
            #pragma unroll
            for (int r = 0; r < 4; r++) acc[i][j][r] = 0.f;

    issue(0);

    for (int c = 0; c < nCh; c++) {
        CP_WAIT0();                 // only copy(c) outstanding
        __syncthreads();            // publishes copy(c); proves compute(c-1) done
        issue(c + 1);               // refill other buffer; overlaps compute(c)

        const uint32_t sbuf = sb + (c & 1) * STG_L;
        #pragma unroll
        for (int k16 = 0; k16 < 2; k16++) {
            uint32_t af[2][4][4];
            uint32_t abase = sbuf + (wm * 64 + (lane & 15)) * PITCH
                           + (k16 * 16 + (lane >> 4) * 8) * 2;
            #pragma unroll
            for (int mt = 0; mt < 4; mt++) {
                ldm4(af[0][mt], abase + mt * 16 * PITCH);
                ldm4(af[1][mt], abase + PLA_L + mt * 16 * PITCH);
            }
            uint32_t bbase = sbuf + 2 * PLA_L
                + (wn * 32 + (lane & 7) + ((lane >> 4) << 3)) * PITCH
                + (k16 * 16 + ((lane >> 3) & 1) * 8) * 2;
            #pragma unroll
            for (int nt2 = 0; nt2 < 2; nt2++) {
                uint32_t bh[4];
                ldm4(bh, bbase + nt2 * 16 * PITCH);
                #pragma unroll
                for (int hf = 0; hf < 2; hf++) {
                    const int nt = nt2 * 2 + hf;
                    #pragma unroll
                    for (int mt = 0; mt < 4; mt++) {
                        mma16816(acc[mt][nt], af[0][mt], &bh[2 * hf]);
                        mma16816(acc[mt][nt], af[1][mt], &bh[2 * hf]);
                    }
                }
            }
        }
    }

    // epilogue
    const long long coff = (long long)(z >> 4) * cO + (long long)(z & 15) * cI;
    #pragma unroll
    for (int nt = 0; nt < 4; nt++) {
        const int gc = bn * 128 + wn * 32 + nt * 8 + (lane & 3) * 2;
        float2 bv = make_float2(0.f, 0.f);
        if (bias) bv = *(const float2*)(bias + gc);
        #pragma unroll
        for (int mt = 0; mt < 4; mt++) {
            const int r0 = bm * 128 + wm * 64 + mt * 16 + (lane >> 2);
            #pragma unroll
            for (int half = 0; half < 2; half++) {
                const long long gp = coff + (long long)(r0 + half * 8) * ldc + gc;
                float v0 = acc[mt][nt][2 * half + 0] * scale + bv.x;
                float v1 = acc[mt][nt][2 * half + 1] * scale + bv.y;
                if (Cf) *(float2*)(Cf + gp) = make_float2(v0, v1);
                if (Csh) {
                    uint2 s = split2(v0, v1);
                    *(uint32_t*)(Csh + gp) = s.x;
                    *(uint32_t*)(Csl + gp) = s.y;
                }
            }
        }
    }
}

__global__ void k_split_x(const float* __restrict__ s, uint16_t* __restrict__ dh,
                          uint16_t* __restrict__ dl, int n2) {
    int i = blockIdx.x * 256 + threadIdx.x;
    if (i < n2) {
        float2 v = *(const float2*)(s + 2 * i);
        uint2 sp = split2(v.x, v.y);
        *(uint32_t*)(dh + 2 * i) = sp.x;
        *(uint32_t*)(dl + 2 * i) = sp.y;
    }
}
// transpose + single-plane fp16 (B-side weights)
__global__ void k_trsp(const float* __restrict__ W, uint16_t* __restrict__ Wth,
                       int Kd, int Nd) {
    __shared__ float t[32][33];
    int n0 = blockIdx.x * 32, k0 = blockIdx.y * 32;
    int tx = threadIdx.x, ty = threadIdx.y;
    #pragma unroll
    for (int i = 0; i < 32; i += 8)
        t[ty + i][tx] = W[(size_t)(k0 + ty + i) * Nd + n0 + tx];
    __syncthreads();
    #pragma unroll
    for (int i = 0; i < 32; i += 8)
        Wth[(size_t)(n0 + ty + i) * Kd + k0 + tx] =
            __half_as_ushort(__float2half_rn(t[tx][ty + i]));
}
__global__ void k_cat3(float* dst, const float* a, const float* b, const float* c,
                       int na, int nb, int nc) {
    int i = blockIdx.x * 256 + threadIdx.x;
    if (i < na) dst[i] = a[i];
    else if (i < na + nb) dst[i] = b[i - na];
    else if (i < na + nb + nc) dst[i] = c[i - na - nb];
}
__global__ void k_cat2(float* dst, const float* a, const float* b, int na, int nb) {
    int i = blockIdx.x * 256 + threadIdx.x;
    if (i < na) dst[i] = a[i];
    else if (i < na + nb) dst[i] = b[i - na];
}
__global__ void k_table() {
    int idx = blockIdx.x * 256 + threadIdx.x;
    int s = idx >> 8, i = idx & 255;
    float dv = expf((float)(2 * i) * (-9.210340371976184f / (float)RRx));
    float sn, cs; sincosf((float)s * dv, &sn, &cs);
    g_sin[idx] = sn; g_cos[idx] = cs;
}
__global__ void k_rope_k() {
    int idx = blockIdx.x * 256 + threadIdx.x;
    int i = idx & 255, row = idx >> 8, s = row & (SSx - 1);
    size_t o = (size_t)row * NDOWN + 1024 + 2 * i;
    float vx = join1(g_d0sh[o],     g_d0sl[o]);
    float vy = join1(g_d0sh[o + 1], g_d0sl[o + 1]);
    float sn = g_sin[s * 256 + i], cs = g_cos[s * 256 + i];
    float2 out; out.x = vx * cs - vy * sn; out.y = vy * cs + vx * sn;
    *(float2*)(g_krr + (size_t)row * RRx + 2 * i) = out;
}
__global__ void k_pack_q() {
    int idx = blockIdx.x * 256 + threadIdx.x;
    int p = idx % 320, s = (idx / 320) & (SSx - 1), z = idx / (320 * SSx);
    int b = z >> 4, h = z & 15;
    size_t ro = (size_t)(b * SSx + s);
    size_t base = ((size_t)z * SSx + s) * QKD;
    if (p < 64) {
        float2 v = *(const float2*)(g_qcf + ro * NQ + h * VHDx + 2 * p);
        uint2 sp = split2(v.x, v.y);
        *(uint32_t*)(g_qfsh + base + 2 * p) = sp.x;
        *(uint32_t*)(g_qfsl + base + 2 * p) = sp.y;
    } else {
        int i = p - 64;
        float2 v = *(const float2*)(g_qcf + ro * NQ + UPx + h * RRx + 2 * i);
        float sn = g_sin[s * 256 + i], cs = g_cos[s * 256 + i];
        uint2 sp = split2(v.x * cs - v.y * sn, v.y * cs + v.x * sn);
        *(uint32_t*)(g_qfsh + base + VHDx + 2 * i) = sp.x;
        *(uint32_t*)(g_qfsl + base + VHDx + 2 * i) = sp.y;
    }
}
__global__ void k_pack_k() {   // B-side: single fp16 plane
    int idx = blockIdx.x * 256 + threadIdx.x;
    int p = idx % 320, s = (idx / 320) & (SSx - 1), z = idx / (320 * SSx);
    int b = z >> 4, h = z & 15;
    size_t ro = (size_t)(b * SSx + s);
    size_t base = ((size_t)z * SSx + s) * QKD;
    if (p < 64) {
        float2 v = *(const float2*)(g_kvf + ro * NKV + h * VHDx + 2 * p);
        *(uint32_t*)(g_kfsh + base + 2 * p) = h2pack(v.x, v.y);
    } else {
        int i = p - 64;
        float2 v = *(const float2*)(g_krr + ro * RRx + 2 * i);
        *(uint32_t*)(g_kfsh + base + VHDx + 2 * i) = h2pack(v.x, v.y);
    }
}
__global__ void k_vt() {       // B-side: single fp16 plane
    __shared__ float t[32][33];
    int z = blockIdx.z, b = z >> 4, h = z & 15;
    int s0 = blockIdx.x * 32, d0 = blockIdx.y * 32;
    int tx = threadIdx.x, ty = threadIdx.y;
    #pragma unroll
    for (int i = 0; i < 32; i += 8)
        t[ty + i][tx] = g_kvf[(size_t)(b * SSx + s0 + ty + i) * NKV + UPx + h * VHDx + d0 + tx];
    __syncthreads();
    #pragma unroll
    for (int i = 0; i < 32; i += 8)
        g_vtsh[(size_t)z * (VHDx * SSx) + (size_t)(d0 + ty + i) * SSx + s0 + tx] =
            __half_as_ushort(__float2half_rn(t[tx][ty + i]));
}
__global__ void __launch_bounds__(128) k_softmax() {
    size_t row = blockIdx.x;
    const float* p = g_sc + row * SSx;
    int t = threadIdx.x;
    float4 v = ((const float4*)p)[t];
    float m = fmaxf(fmaxf(v.x, v.y), fmaxf(v.z, v.w));
    #pragma unroll
    for (int o = 16; o; o >>= 1) m = fmaxf(m, __shfl_xor_sync(0xffffffffu, m, o));
    __shared__ float rm[4], rs[4];
    if ((t & 31) == 0) rm[t >> 5] = m;
    __syncthreads();
    m = fmaxf(fmaxf(rm[0], rm[1]), fmaxf(rm[2], rm[3]));
    v.x = __expf(v.x - m); v.y = __expf(v.y - m);
    v.z = __expf(v.z - m); v.w = __expf(v.w - m);
    float s = v.x + v.y + v.z + v.w;
    #pragma unroll
    for (int o = 16; o; o >>= 1) s += __shfl_xor_sync(0xffffffffu, s, o);
    if ((t & 31) == 0) rs[t >> 5] = s;
    __syncthreads();
    s = rs[0] + rs[1] + rs[2] + rs[3];
    float inv = 1.f / s;
    uint2 s01 = split2(v.x * inv, v.y * inv);
    uint2 s23 = split2(v.z * inv, v.w * inv);
    *(uint2*)(g_psh + row * SSx + t * 4) = make_uint2(s01.x, s23.x);
    *(uint2*)(g_psl + row * SSx + t * 4) = make_uint2(s01.y, s23.y);
}

extern "C" void kernel_launch(void* const* d_in, const int* in_sizes, int n_in,
                              void* d_out, int out_size)
{
    const float* X    = (const float*)d_in[0];
    const float* Wdq  = (const float*)d_in[1];
    const float* bdq  = (const float*)d_in[2];
    const float* Wdkv = (const float*)d_in[3];
    const float* bdkv = (const float*)d_in[4];
    const float* Wuq  = (const float*)d_in[5];
    const float* buq  = (const float*)d_in[6];
    const float* Wuk  = (const float*)d_in[7];
    const float* buk  = (const float*)d_in[8];
    const float* Wuv  = (const float*)d_in[9];
    const float* buv  = (const float*)d_in[10];
    const float* Wqr  = (const float*)d_in[11];
    const float* bqr  = (const float*)d_in[12];
    const float* Wkr  = (const float*)d_in[13];
    const float* bkr  = (const float*)d_in[14];
    const float* Wfc  = (const float*)d_in[15];
    const float* bfc  = (const float*)d_in[16];
    float* out = (float*)d_out;

    cudaFuncSetAttribute(k_gemm, cudaFuncAttributeMaxDynamicSharedMemorySize, SMEMB);

    #define SYM(v, g) void* v; cudaGetSymbolAddress(&v, g)
    SYM(p_xsh, g_xsh);   SYM(p_xsl, g_xsl);
    SYM(p_wdth, g_wdth); SYM(p_bd, g_bd);
    SYM(p_wqth, g_wqth); SYM(p_wkvth, g_wkvth);
    SYM(p_bq, g_bq); SYM(p_bkv, g_bkv);
    SYM(p_wfcth, g_wfcth);
    SYM(p_d0sh, g_d0sh); SYM(p_d0sl, g_d0sl);
    SYM(p_qcf, g_qcf); SYM(p_kvf, g_kvf);
    SYM(p_qfsh, g_qfsh); SYM(p_qfsl, g_qfsl);
    SYM(p_kfsh, g_kfsh);
    SYM(p_sc, g_sc); SYM(p_psh, g_psh); SYM(p_psl, g_psl);
    SYM(p_vtsh, g_vtsh);
    SYM(p_ofsh, g_ofsh); SYM(p_ofsl, g_ofsl);
    #undef SYM

    dim3 tb(32, 8);
    k_table<<<SSx, 256>>>();
    k_split_x<<<(MROWS * DDx / 2) / 256, 256>>>(X, (uint16_t*)p_xsh, (uint16_t*)p_xsl,
                                                MROWS * DDx / 2);
    k_trsp<<<dim3(16, 64), tb>>>(Wdq,  (uint16_t*)p_wdth, 2048, 512);
    k_trsp<<<dim3(16, 64), tb>>>(Wdkv, (uint16_t*)p_wdth + (size_t)512 * 2048, 2048, 512);
    k_trsp<<<dim3(16, 64), tb>>>(Wkr,  (uint16_t*)p_wdth + (size_t)1024 * 2048, 2048, 512);
    k_trsp<<<dim3(64, 16), tb>>>(Wuq, (uint16_t*)p_wqth, 512, 2048);
    k_trsp<<<dim3(256, 16), tb>>>(Wqr, (uint16_t*)p_wqth + (size_t)UPx * 512, 512, 8192);
    k_trsp<<<dim3(64, 16), tb>>>(Wuk, (uint16_t*)p_wkvth, 512, 2048);
    k_trsp<<<dim3(64, 16), tb>>>(Wuv, (uint16_t*)p_wkvth + (size_t)UPx * 512, 512, 2048);
    k_trsp<<<dim3(64, 64), tb>>>(Wfc, (uint16_t*)p_wfcth, 2048, 2048);
    k_cat3<<<(NDOWN + 255) / 256, 256>>>((float*)p_bd, bdq, bdkv, bkr, 512, 512, 512);
    k_cat2<<<(NQ + 255) / 256, 256>>>((float*)p_bq, buq, bqr, UPx, RRx * HHx);
    k_cat2<<<(NKV + 255) / 256, 256>>>((float*)p_bkv, buk, buv, UPx, UPx);

    // fused down-proj: M=4096, N=1536, K=2048 (split output only)
    k_gemm<<<dim3(12, 32, 1), 256, SMEMB>>>(
        (uint16_t*)p_xsh, (uint16_t*)p_xsl, DDx, 0,
        (uint16_t*)p_wdth, DDx, 0,
        nullptr, (uint16_t*)p_d0sh, (uint16_t*)p_d0sl, NDOWN, 0, 0,
        (float*)p_bd, 1.f, DDx);

    // merged q-side up-proj: M=4096, N=10240, K=512
    k_gemm<<<dim3(80, 32, 1), 256, SMEMB>>>(
        (uint16_t*)p_d0sh, (uint16_t*)p_d0sl, NDOWN, 0,
        (uint16_t*)p_wqth, DWN, 0,
        (float*)p_qcf, nullptr, nullptr, NQ, 0, 0, (float*)p_bq, 1.f, DWN);
    // merged kv-side up-proj: M=4096, N=4096, K=512
    k_gemm<<<dim3(32, 32, 1), 256, SMEMB>>>(
        (uint16_t*)p_d0sh + 512, (uint16_t*)p_d0sl + 512, NDOWN, 0,
        (uint16_t*)p_wkvth, DWN, 0,
        (float*)p_kvf, nullptr, nullptr, NKV, 0, 0, (float*)p_bkv, 1.f, DWN);

    k_rope_k<<<MROWS, 256>>>();
    k_pack_q<<<(ZBx * SSx * 320) / 256, 256>>>();
    k_pack_k<<<(ZBx * SSx * 320) / 256, 256>>>();
    k_vt<<<dim3(16, 4, ZBx), tb>>>();

    // scores: per z M=512, N=512, K=640
    k_gemm<<<dim3(4, 4, ZBx), 256, SMEMB>>>(
        (uint16_t*)p_qfsh, (uint16_t*)p_qfsl, QKD, (long long)SSx * QKD,
        (uint16_t*)p_kfsh, QKD, (long long)SSx * QKD,
        (float*)p_sc, nullptr, nullptr, SSx,
        (long long)16 * SSx * SSx, (long long)SSx * SSx,
        nullptr, INV_SCALE, QKD);

    k_softmax<<<ZBx * SSx, 128>>>();

    // PV: per z M=512, N=128, K=512 -> split store scattered to [b,s,h*128+d]
    k_gemm<<<dim3(1, 4, ZBx), 256, SMEMB>>>(
        (uint16_t*)p_psh, (uint16_t*)p_psl, SSx, (long long)SSx * SSx,
        (uint16_t*)p_vtsh, SSx, (long long)VHDx * SSx,
        nullptr, (uint16_t*)p_ofsh, (uint16_t*)p_ofsl, UPx,
        (long long)SSx * UPx, (long long)VHDx,
        nullptr, 1.f, SSx);

    // final: M=4096, N=2048, K=2048 -> out fp32
    k_gemm<<<dim3(16, 32, 1), 256, SMEMB>>>(
        (uint16_t*)p_ofsh, (uint16_t*)p_ofsl, UPx, 0,
        (uint16_t*)p_wfcth, DDx, 0,
        out, nullptr, nullptr, DDx, 0, 0, bfc, 1.f, DDx);
}

// round 9
// speedup vs baseline: 3.9301x; 1.0376x over previous
#include <cuda_runtime.h>
#include <cuda_fp16.h>
#include <cstdint>
#include <math.h>

#define BBx   8
#define SSx   512
#define DDx   2048
#define HHx   16
#define DWN   512
#define UPx   2048
#define RRx   512
#define VHDx  128
#define MROWS (BBx*SSx)
#define ZBx   (BBx*HHx)
#define QKD   (VHDx+RRx)
#define NDOWN (DWN*3)
#define NQ    (UPx + RRx*HHx)     // 10240  (qc | qr)
#define NKV   (UPx + UPx)         // 4096   (kc | vc)
#define INV_SCALE 0.0294627825494394758f

// A-side tensors: fp16 hi+lo planes (exact). B-side tensors: single fp16 plane.
__device__ uint16_t g_xsh [(size_t)MROWS*DDx];
__device__ uint16_t g_xsl [(size_t)MROWS*DDx];
__device__ uint16_t g_wdth[(size_t)NDOWN*DDx];      // B
__device__ float    g_bd  [NDOWN];
__device__ uint16_t g_wqth[(size_t)NQ*DWN];         // B
__device__ uint16_t g_wkvth[(size_t)NKV*DWN];       // B
__device__ float    g_bq  [NQ];
__device__ float    g_bkv [NKV];
__device__ uint16_t g_wfcth[(size_t)DDx*DDx];       // B
__device__ uint16_t g_d0sh[(size_t)MROWS*NDOWN];
__device__ uint16_t g_d0sl[(size_t)MROWS*NDOWN];
__device__ float    g_qcf [(size_t)MROWS*NQ];
__device__ float    g_kvf [(size_t)MROWS*NKV];
__device__ float    g_krr [(size_t)MROWS*RRx];
__device__ uint16_t g_qfsh[(size_t)ZBx*SSx*QKD];
__device__ uint16_t g_qfsl[(size_t)ZBx*SSx*QKD];
__device__ uint16_t g_kfsh[(size_t)ZBx*SSx*QKD];    // B
__device__ float    g_sc  [(size_t)ZBx*SSx*SSx];
__device__ uint16_t g_psh [(size_t)ZBx*SSx*SSx];
__device__ uint16_t g_psl [(size_t)ZBx*SSx*SSx];
__device__ uint16_t g_vtsh[(size_t)ZBx*VHDx*SSx];   // B
__device__ uint16_t g_ofsh[(size_t)MROWS*UPx];
__device__ uint16_t g_ofsl[(size_t)MROWS*UPx];
__device__ float    g_sin [SSx*(RRx/2)];
__device__ float    g_cos [SSx*(RRx/2)];

__device__ __forceinline__ uint32_t smem_u32(const void* p) {
    uint32_t a;
    asm("{ .reg .u64 t; cvta.to.shared.u64 t, %1; cvt.u32.u64 %0, t; }" : "=r"(a) : "l"(p));
    return a;
}
__device__ __forceinline__ void split1(float v, uint16_t& h, uint16_t& l) {
    __half hb = __float2half_rn(v);
    __half lb = __float2half_rn(v - __half2float(hb));
    h = __half_as_ushort(hb); l = __half_as_ushort(lb);
}
__device__ __forceinline__ uint2 split2(float a, float b) {
    uint16_t ah, al, bh, bl; split1(a, ah, al); split1(b, bh, bl);
    return make_uint2((uint32_t)ah | ((uint32_t)bh << 16),
                      (uint32_t)al | ((uint32_t)bl << 16));
}
__device__ __forceinline__ uint32_t h2pack(float a, float b) {
    __half2 h = __floats2half2_rn(a, b);
    return *(uint32_t*)&h;
}
__device__ __forceinline__ float join1(uint16_t h, uint16_t l) {
    return __half2float(__ushort_as_half(h)) + __half2float(__ushort_as_half(l));
}
__device__ __forceinline__ void ldm4(uint32_t* r, uint32_t addr) {
    asm volatile("ldmatrix.sync.aligned.m8n8.x4.shared.b16 {%0,%1,%2,%3}, [%4];"
        : "=r"(r[0]), "=r"(r[1]), "=r"(r[2]), "=r"(r[3]) : "r"(addr));
}
__device__ __forceinline__ void mma16816(float* c, const uint32_t* a, const uint32_t* b) {
    asm volatile("mma.sync.aligned.m16n8k16.row.col.f32.f16.f16.f32 "
        "{%0,%1,%2,%3}, {%4,%5,%6,%7}, {%8,%9}, {%0,%1,%2,%3};"
        : "+f"(c[0]), "+f"(c[1]), "+f"(c[2]), "+f"(c[3])
        : "r"(a[0]), "r"(a[1]), "r"(a[2]), "r"(a[3]), "r"(b[0]), "r"(b[1]));
}
#define CP16(dst, src) \
    asm volatile("cp.async.cg.shared.global [%0], [%1], 16;" :: "r"(dst), "l"(src))
#define CP_COMMIT() asm volatile("cp.async.commit_group;" ::: "memory")
#define CP_WAIT0()  asm volatile("cp.async.wait_group 0;" ::: "memory")

// smem plane: 128 rows x 80B pitch (64B payload = 32 fp16). Planes: Ah, Al, Bh.
#define PITCH  80
#define PLA_L  (128*PITCH)
#define STG_L  (3*PLA_L)          // 30720 per stage
#define SMEMB  (2*STG_L)          // 61440 -> 2 CTAs/SM

// C = scale*(A @ B^T) + bias.  A: fp16 hi+lo planes (exact); B: fp16. BM=BN=128, BK=32.
// Warp grid 4m x 2n (warp tile 32x64): split operand on the NARROW side to cut ldsm traffic.
__global__ void __launch_bounds__(256, 2) k_gemm(
    const uint16_t* __restrict__ Ah, const uint16_t* __restrict__ Al, int lda, long long aB,
    const uint16_t* __restrict__ Bh, int ldb, long long bB,
    float* Cf, uint16_t* Csh, uint16_t* Csl, int ldc, long long cO, long long cI,
    const float* __restrict__ bias, float scale, int K)
{
    extern __shared__ __align__(16) char smem[];
    const uint32_t sb = smem_u32(smem);
    const int tid = threadIdx.x, lane = tid & 31, wid = tid >> 5;
    const int wm = wid >> 1, wn = wid & 1;     // 4m x 2n
    const int z = blockIdx.z, bm = blockIdx.y, bn = blockIdx.x;

    const uint16_t* pb0 = Ah + (size_t)z * aB + (size_t)bm * 128 * lda;
    const uint16_t* pb1 = Al + (size_t)z * aB + (size_t)bm * 128 * lda;
    const uint16_t* pb2 = Bh + (size_t)z * bB + (size_t)bn * 128 * ldb;
    const int nCh = K / 32;

    auto issue = [&](int c) {
        if (c < nCh) {
            const int kc = c * 32;
            const uint32_t sdst = sb + (c & 1) * STG_L;
            const int row = (tid >> 2);           // 0..63
            const int col16 = (tid & 3);          // 16B column
            #pragma unroll
            for (int p = 0; p < 6; p++) {
                const int pl = p >> 1;
                const int r = (p & 1) * 64 + row;
                const uint16_t* src = (pl == 0 ? pb0 : pl == 1 ? pb1 : pb2);
                const int ld = (pl < 2) ? lda : ldb;
                CP16(sdst + pl * PLA_L + r * PITCH + col16 * 16,
                     src + (size_t)r * ld + kc + col16 * 8);
            }
            CP_COMMIT();
        }
    };

    float acc[2][8][4];
    #pragma unroll
    for (int i = 0; i < 2; i++)
        #pragma unroll
        for (int j = 0; j < 8; j++)
            #pragma unroll
            for (int r = 0; r < 4; r++) acc[i][j][r] = 0.f;

    issue(0);

    for (int c = 0; c < nCh; c++) {
        CP_WAIT0();                 // only copy(c) outstanding
        __syncthreads();            // publishes copy(c); proves compute(c-1) done
        issue(c + 1);               // refill other buffer; overlaps compute(c)

        const uint32_t sbuf = sb + (c & 1) * STG_L;
        #pragma unroll
        for (int k16 = 0; k16 < 2; k16++) {
            uint32_t af[2][2][4];
            uint32_t abase = sbuf + (wm * 32 + (lane & 15)) * PITCH
                           + (k16 * 16 + (lane >> 4) * 8) * 2;
            #pragma unroll
            for (int mt = 0; mt < 2; mt++) {
                ldm4(af[0][mt], abase + mt * 16 * PITCH);
                ldm4(af[1][mt], abase + PLA_L + mt * 16 * PITCH);
            }
            uint32_t bbase = sbuf + 2 * PLA_L
                + (wn * 64 + (lane & 7) + ((lane >> 4) << 3)) * PITCH
                + (k16 * 16 + ((lane >> 3) & 1) * 8) * 2;
            #pragma unroll
            for (int nb = 0; nb < 4; nb++) {
                uint32_t bh[4];
                ldm4(bh, bbase + nb * 16 * PITCH);
                #pragma unroll
                for (int hf = 0; hf < 2; hf++) {
                    const int nt = nb * 2 + hf;
                    #pragma unroll
                    for (int mt = 0; mt < 2; mt++) {
                        mma16816(acc[mt][nt], af[0][mt], &bh[2 * hf]);
                        mma16816(acc[mt][nt], af[1][mt], &bh[2 * hf]);
                    }
                }
            }
        }
    }

    // epilogue
    const long long coff = (long long)(z >> 4) * cO + (long long)(z & 15) * cI;
    #pragma unroll
    for (int nt = 0; nt < 8; nt++) {
        const int gc = bn * 128 + wn * 64 + nt * 8 + (lane & 3) * 2;
        float2 bv = make_float2(0.f, 0.f);
        if (bias) bv = *(const float2*)(bias + gc);
        #pragma unroll
        for (int mt = 0; mt < 2; mt++) {
            const int r0 = bm * 128 + wm * 32 + mt * 16 + (lane >> 2);
            #pragma unroll
            for (int half = 0; half < 2; half++) {
                const long long gp = coff + (long long)(r0 + half * 8) * ldc + gc;
                float v0 = acc[mt][nt][2 * half + 0] * scale + bv.x;
                float v1 = acc[mt][nt][2 * half + 1] * scale + bv.y;
                if (Cf) *(float2*)(Cf + gp) = make_float2(v0, v1);
                if (Csh) {
                    uint2 s = split2(v0, v1);
                    *(uint32_t*)(Csh + gp) = s.x;
                    *(uint32_t*)(Csl + gp) = s.y;
                }
            }
        }
    }
}

__global__ void k_split_x(const float* __restrict__ s, uint16_t* __restrict__ dh,
                          uint16_t* __restrict__ dl, int n2) {
    int i = blockIdx.x * 256 + threadIdx.x;
    if (i < n2) {
        float2 v = *(const float2*)(s + 2 * i);
        uint2 sp = split2(v.x, v.y);
        *(uint32_t*)(dh + 2 * i) = sp.x;
        *(uint32_t*)(dl + 2 * i) = sp.y;
    }
}
// transpose + single-plane fp16 (B-side weights)
__global__ void k_trsp(const float* __restrict__ W, uint16_t* __restrict__ Wth,
                       int Kd, int Nd) {
    __shared__ float t[32][33];
    int n0 = blockIdx.x * 32, k0 = blockIdx.y * 32;
    int tx = threadIdx.x, ty = threadIdx.y;
    #pragma unroll
    for (int i = 0; i < 32; i += 8)
        t[ty + i][tx] = W[(size_t)(k0 + ty + i) * Nd + n0 + tx];
    __syncthreads();
    #pragma unroll
    for (int i = 0; i < 32; i += 8)
        Wth[(size_t)(n0 + ty + i) * Kd + k0 + tx] =
            __half_as_ushort(__float2half_rn(t[tx][ty + i]));
}
__global__ void k_cat3(float* dst, const float* a, const float* b, const float* c,
                       int na, int nb, int nc) {
    int i = blockIdx.x * 256 + threadIdx.x;
    if (i < na) dst[i] = a[i];
    else if (i < na + nb) dst[i] = b[i - na];
    else if (i < na + nb + nc) dst[i] = c[i - na - nb];
}
__global__ void k_cat2(float* dst, const float* a, const float* b, int na, int nb) {
    int i = blockIdx.x * 256 + threadIdx.x;
    if (i < na) dst[i] = a[i];
    else if (i < na + nb) dst[i] = b[i - na];
}
__global__ void k_table() {
    int idx = blockIdx.x * 256 + threadIdx.x;
    int s = idx >> 8, i = idx & 255;
    float dv = expf((float)(2 * i) * (-9.210340371976184f / (float)RRx));
    float sn, cs; sincosf((float)s * dv, &sn, &cs);
    g_sin[idx] = sn; g_cos[idx] = cs;
}
__global__ void k_rope_k() {
    int idx = blockIdx.x * 256 + threadIdx.x;
    int i = idx & 255, row = idx >> 8, s = row & (SSx - 1);
    size_t o = (size_t)row * NDOWN + 1024 + 2 * i;
    float vx = join1(g_d0sh[o],     g_d0sl[o]);
    float vy = join1(g_d0sh[o + 1], g_d0sl[o + 1]);
    float sn = g_sin[s * 256 + i], cs = g_cos[s * 256 + i];
    float2 out; out.x = vx * cs - vy * sn; out.y = vy * cs + vx * sn;
    *(float2*)(g_krr + (size_t)row * RRx + 2 * i) = out;
}
__global__ void k_pack_q() {
    int idx = blockIdx.x * 256 + threadIdx.x;
    int p = idx % 320, s = (idx / 320) & (SSx - 1), z = idx / (320 * SSx);
    int b = z >> 4, h = z & 15;
    size_t ro = (size_t)(b * SSx + s);
    size_t base = ((size_t)z * SSx + s) * QKD;
    if (p < 64) {
        float2 v = *(const float2*)(g_qcf + ro * NQ + h * VHDx + 2 * p);
        uint2 sp = split2(v.x, v.y);
        *(uint32_t*)(g_qfsh + base + 2 * p) = sp.x;
        *(uint32_t*)(g_qfsl + base + 2 * p) = sp.y;
    } else {
        int i = p - 64;
        float2 v = *(const float2*)(g_qcf + ro * NQ + UPx + h * RRx + 2 * i);
        float sn = g_sin[s * 256 + i], cs = g_cos[s * 256 + i];
        uint2 sp = split2(v.x * cs - v.y * sn, v.y * cs + v.x * sn);
        *(uint32_t*)(g_qfsh + base + VHDx + 2 * i) = sp.x;
        *(uint32_t*)(g_qfsl + base + VHDx + 2 * i) = sp.y;
    }
}
__global__ void k_pack_k() {   // B-side: single fp16 plane
    int idx = blockIdx.x * 256 + threadIdx.x;
    int p = idx % 320, s = (idx / 320) & (SSx - 1), z = idx / (320 * SSx);
    int b = z >> 4, h = z & 15;
    size_t ro = (size_t)(b * SSx + s);
    size_t base = ((size_t)z * SSx + s) * QKD;
    if (p < 64) {
        float2 v = *(const float2*)(g_kvf + ro * NKV + h * VHDx + 2 * p);
        *(uint32_t*)(g_kfsh + base + 2 * p) = h2pack(v.x, v.y);
    } else {
        int i = p - 64;
        float2 v = *(const float2*)(g_krr + ro * RRx + 2 * i);
        *(uint32_t*)(g_kfsh + base + VHDx + 2 * i) = h2pack(v.x, v.y);
    }
}
__global__ void k_vt() {       // B-side: single fp16 plane
    __shared__ float t[32][33];
    int z = blockIdx.z, b = z >> 4, h = z & 15;
    int s0 = blockIdx.x * 32, d0 = blockIdx.y * 32;
    int tx = threadIdx.x, ty = threadIdx.y;
    #pragma unroll
    for (int i = 0; i < 32; i += 8)
        t[ty + i][tx] = g_kvf[(size_t)(b * SSx + s0 + ty + i) * NKV + UPx + h * VHDx + d0 + tx];
    __syncthreads();
    #pragma unroll
    for (int i = 0; i < 32; i += 8)
        g_vtsh[(size_t)z * (VHDx * SSx) + (size_t)(d0 + ty + i) * SSx + s0 + tx] =
            __half_as_ushort(__float2half_rn(t[tx][ty + i]));
}
__global__ void __launch_bounds__(128) k_softmax() {
    size_t row = blockIdx.x;
    const float* p = g_sc + row * SSx;
    int t = threadIdx.x;
    float4 v = ((const float4*)p)[t];
    float m = fmaxf(fmaxf(v.x, v.y), fmaxf(v.z, v.w));
    #pragma unroll
    for (int o = 16; o; o >>= 1) m = fmaxf(m, __shfl_xor_sync(0xffffffffu, m, o));
    __shared__ float rm[4], rs[4];
    if ((t & 31) == 0) rm[t >> 5] = m;
    __syncthreads();
    m = fmaxf(fmaxf(rm[0], rm[1]), fmaxf(rm[2], rm[3]));
    v.x = __expf(v.x - m); v.y = __expf(v.y - m);
    v.z = __expf(v.z - m); v.w = __expf(v.w - m);
    float s = v.x + v.y + v.z + v.w;
    #pragma unroll
    for (int o = 16; o; o >>= 1) s += __shfl_xor_sync(0xffffffffu, s, o);
    if ((t & 31) == 0) rs[t >> 5] = s;
    __syncthreads();
    s = rs[0] + rs[1] + rs[2] + rs[3];
    float inv = 1.f / s;
    uint2 s01 = split2(v.x * inv, v.y * inv);
    uint2 s23 = split2(v.z * inv, v.w * inv);
    *(uint2*)(g_psh + row * SSx + t * 4) = make_uint2(s01.x, s23.x);
    *(uint2*)(g_psl + row * SSx + t * 4) = make_uint2(s01.y, s23.y);
}

extern "C" void kernel_launch(void* const* d_in, const int* in_sizes, int n_in,
                              void* d_out, int out_size)
{
    const float* X    = (const float*)d_in[0];
    const float* Wdq  = (const float*)d_in[1];
    const float* bdq  = (const float*)d_in[2];
    const float* Wdkv = (const float*)d_in[3];
    const float* bdkv = (const float*)d_in[4];
    const float* Wuq  = (const float*)d_in[5];
    const float* buq  = (const float*)d_in[6];
    const float* Wuk  = (const float*)d_in[7];
    const float* buk  = (const float*)d_in[8];
    const float* Wuv  = (const float*)d_in[9];
    const float* buv  = (const float*)d_in[10];
    const float* Wqr  = (const float*)d_in[11];
    const float* bqr  = (const float*)d_in[12];
    const float* Wkr  = (const float*)d_in[13];
    const float* bkr  = (const float*)d_in[14];
    const float* Wfc  = (const float*)d_in[15];
    const float* bfc  = (const float*)d_in[16];
    float* out = (float*)d_out;

    cudaFuncSetAttribute(k_gemm, cudaFuncAttributeMaxDynamicSharedMemorySize, SMEMB);

    #define SYM(v, g) void* v; cudaGetSymbolAddress(&v, g)
    SYM(p_xsh, g_xsh);   SYM(p_xsl, g_xsl);
    SYM(p_wdth, g_wdth); SYM(p_bd, g_bd);
    SYM(p_wqth, g_wqth); SYM(p_wkvth, g_wkvth);
    SYM(p_bq, g_bq); SYM(p_bkv, g_bkv);
    SYM(p_wfcth, g_wfcth);
    SYM(p_d0sh, g_d0sh); SYM(p_d0sl, g_d0sl);
    SYM(p_qcf, g_qcf); SYM(p_kvf, g_kvf);
    SYM(p_qfsh, g_qfsh); SYM(p_qfsl, g_qfsl);
    SYM(p_kfsh, g_kfsh);
    SYM(p_sc, g_sc); SYM(p_psh, g_psh); SYM(p_psl, g_psl);
    SYM(p_vtsh, g_vtsh);
    SYM(p_ofsh, g_ofsh); SYM(p_ofsl, g_ofsl);
    #undef SYM

    dim3 tb(32, 8);
    k_table<<<SSx, 256>>>();
    k_split_x<<<(MROWS * DDx / 2) / 256, 256>>>(X, (uint16_t*)p_xsh, (uint16_t*)p_xsl,
                                                MROWS * DDx / 2);
    k_trsp<<<dim3(16, 64), tb>>>(Wdq,  (uint16_t*)p_wdth, 2048, 512);
    k_trsp<<<dim3(16, 64), tb>>>(Wdkv, (uint16_t*)p_wdth + (size_t)512 * 2048, 2048, 512);
    k_trsp<<<dim3(16, 64), tb>>>(Wkr,  (uint16_t*)p_wdth + (size_t)1024 * 2048, 2048, 512);
    k_trsp<<<dim3(64, 16), tb>>>(Wuq, (uint16_t*)p_wqth, 512, 2048);
    k_trsp<<<dim3(256, 16), tb>>>(Wqr, (uint16_t*)p_wqth + (size_t)UPx * 512, 512, 8192);
    k_trsp<<<dim3(64, 16), tb>>>(Wuk, (uint16_t*)p_wkvth, 512, 2048);
    k_trsp<<<dim3(64, 16), tb>>>(Wuv, (uint16_t*)p_wkvth + (size_t)UPx * 512, 512, 2048);
    k_trsp<<<dim3(64, 64), tb>>>(Wfc, (uint16_t*)p_wfcth, 2048, 2048);
    k_cat3<<<(NDOWN + 255) / 256, 256>>>((float*)p_bd, bdq, bdkv, bkr, 512, 512, 512);
    k_cat2<<<(NQ + 255) / 256, 256>>>((float*)p_bq, buq, bqr, UPx, RRx * HHx);
    k_cat2<<<(NKV + 255) / 256, 256>>>((float*)p_bkv, buk, buv, UPx, UPx);

    // fused down-proj: M=4096, N=1536, K=2048 (split output only)
    k_gemm<<<dim3(12, 32, 1), 256, SMEMB>>>(
        (uint16_t*)p_xsh, (uint16_t*)p_xsl, DDx, 0,
        (uint16_t*)p_wdth, DDx, 0,
        nullptr, (uint16_t*)p_d0sh, (uint16_t*)p_d0sl, NDOWN, 0, 0,
        (float*)p_bd, 1.f, DDx);

    // merged q-side up-proj: M=4096, N=10240, K=512
    k_gemm<<<dim3(80, 32, 1), 256, SMEMB>>>(
        (uint16_t*)p_d0sh, (uint16_t*)p_d0sl, NDOWN, 0,
        (uint16_t*)p_wqth, DWN, 0,
        (float*)p_qcf, nullptr, nullptr, NQ, 0, 0, (float*)p_bq, 1.f, DWN);
    // merged kv-side up-proj: M=4096, N=4096, K=512
    k_gemm<<<dim3(32, 32, 1), 256, SMEMB>>>(
        (uint16_t*)p_d0sh + 512, (uint16_t*)p_d0sl + 512, NDOWN, 0,
        (uint16_t*)p_wkvth, DWN, 0,
        (float*)p_kvf, nullptr, nullptr, NKV, 0, 0, (float*)p_bkv, 1.f, DWN);

    k_rope_k<<<MROWS, 256>>>();
    k_pack_q<<<(ZBx * SSx * 320) / 256, 256>>>();
    k_pack_k<<<(ZBx * SSx * 320) / 256, 256>>>();
    k_vt<<<dim3(16, 4, ZBx), tb>>>();

    // scores: per z M=512, N=512, K=640
    k_gemm<<<dim3(4, 4, ZBx), 256, SMEMB>>>(
        (uint16_t*)p_qfsh, (uint16_t*)p_qfsl, QKD, (long long)SSx * QKD,
        (uint16_t*)p_kfsh, QKD, (long long)SSx * QKD,
        (float*)p_sc, nullptr, nullptr, SSx,
        (long long)16 * SSx * SSx, (long long)SSx * SSx,
        nullptr, INV_SCALE, QKD);

    k_softmax<<<ZBx * SSx, 128>>>();

    // PV: per z M=512, N=128, K=512 -> split store scattered to [b,s,h*128+d]
    k_gemm<<<dim3(1, 4, ZBx), 256, SMEMB>>>(
        (uint16_t*)p_psh, (uint16_t*)p_psl, SSx, (long long)SSx * SSx,
        (uint16_t*)p_vtsh, SSx, (long long)VHDx * SSx,
        nullptr, (uint16_t*)p_ofsh, (uint16_t*)p_ofsl, UPx,
        (long long)SSx * UPx, (long long)VHDx,
        nullptr, 1.f, SSx);

    // final: M=4096, N=2048, K=2048 -> out fp32
    k_gemm<<<dim3(16, 32, 1), 256, SMEMB>>>(
        (uint16_t*)p_ofsh, (uint16_t*)p_ofsl, UPx, 0,
        (uint16_t*)p_wfcth, DDx, 0,
        out, nullptr, nullptr, DDx, 0, 0, bfc, 1.f, DDx);
}

// round 10
// speedup vs baseline: 4.1659x; 1.0600x over previous
#include <cuda_runtime.h>
#include <cuda_fp16.h>
#include <cstdint>
#include <math.h>

#define BBx   8
#define SSx   512
#define DDx   2048
#define HHx   16
#define DWN   512
#define UPx   2048
#define RRx   512
#define VHDx  128
#define MROWS (BBx*SSx)
#define ZBx   (BBx*HHx)
#define QKD   (VHDx+RRx)
#define NDOWN (DWN*3)
#define NQ    (UPx + RRx*HHx)     // 10240  (qc | qr)
#define NKV   (UPx + UPx)         // 4096   (kc | vc)
#define INV_SCALE 0.0294627825494394758f

// A-side tensors: fp16 hi+lo planes (exact). B-side tensors: single fp16 plane.
__device__ uint16_t g_xsh [(size_t)MROWS*DDx];
__device__ uint16_t g_xsl [(size_t)MROWS*DDx];
__device__ uint16_t g_wdth[(size_t)NDOWN*DDx];      // B
__device__ float    g_bd  [NDOWN];
__device__ uint16_t g_wqth[(size_t)NQ*DWN];         // B
__device__ uint16_t g_wkvth[(size_t)NKV*DWN];       // B
__device__ float    g_bq  [NQ];
__device__ float    g_bkv [NKV];
__device__ uint16_t g_wfcth[(size_t)DDx*DDx];       // B
__device__ uint16_t g_d0sh[(size_t)MROWS*NDOWN];
__device__ uint16_t g_d0sl[(size_t)MROWS*NDOWN];
// q-up output: roped, split planes [4096][10240]
__device__ uint16_t g_quh [(size_t)MROWS*NQ];
__device__ uint16_t g_qul [(size_t)MROWS*NQ];
// kv-up output: K content fp16 [4096][2048], V fp32 [4096][2048]
__device__ uint16_t g_kch [(size_t)MROWS*UPx];
__device__ float    g_vf  [(size_t)MROWS*UPx];
// roped k_r, fp16 [4096][512] (shared across heads)
__device__ uint16_t g_krh [(size_t)MROWS*RRx];
__device__ float    g_sc  [(size_t)ZBx*SSx*SSx];
__device__ uint16_t g_psh [(size_t)ZBx*SSx*SSx];
__device__ uint16_t g_psl [(size_t)ZBx*SSx*SSx];
__device__ uint16_t g_vtsh[(size_t)ZBx*VHDx*SSx];   // B
__device__ uint16_t g_ofsh[(size_t)MROWS*UPx];
__device__ uint16_t g_ofsl[(size_t)MROWS*UPx];
__device__ float    g_sin [SSx*(RRx/2)];
__device__ float    g_cos [SSx*(RRx/2)];

__device__ __forceinline__ uint32_t smem_u32(const void* p) {
    uint32_t a;
    asm("{ .reg .u64 t; cvta.to.shared.u64 t, %1; cvt.u32.u64 %0, t; }" : "=r"(a) : "l"(p));
    return a;
}
__device__ __forceinline__ void split1(float v, uint16_t& h, uint16_t& l) {
    __half hb = __float2half_rn(v);
    __half lb = __float2half_rn(v - __half2float(hb));
    h = __half_as_ushort(hb); l = __half_as_ushort(lb);
}
__device__ __forceinline__ uint2 split2(float a, float b) {
    uint16_t ah, al, bh, bl; split1(a, ah, al); split1(b, bh, bl);
    return make_uint2((uint32_t)ah | ((uint32_t)bh << 16),
                      (uint32_t)al | ((uint32_t)bl << 16));
}
__device__ __forceinline__ uint32_t h2pack(float a, float b) {
    __half2 h = __floats2half2_rn(a, b);
    return *(uint32_t*)&h;
}
__device__ __forceinline__ float join1(uint16_t h, uint16_t l) {
    return __half2float(__ushort_as_half(h)) + __half2float(__ushort_as_half(l));
}
__device__ __forceinline__ void ldm4(uint32_t* r, uint32_t addr) {
    asm volatile("ldmatrix.sync.aligned.m8n8.x4.shared.b16 {%0,%1,%2,%3}, [%4];"
        : "=r"(r[0]), "=r"(r[1]), "=r"(r[2]), "=r"(r[3]) : "r"(addr));
}
__device__ __forceinline__ void mma16816(float* c, const uint32_t* a, const uint32_t* b) {
    asm volatile("mma.sync.aligned.m16n8k16.row.col.f32.f16.f16.f32 "
        "{%0,%1,%2,%3}, {%4,%5,%6,%7}, {%8,%9}, {%0,%1,%2,%3};"
        : "+f"(c[0]), "+f"(c[1]), "+f"(c[2]), "+f"(c[3])
        : "r"(a[0]), "r"(a[1]), "r"(a[2]), "r"(a[3]), "r"(b[0]), "r"(b[1]));
}
#define CP16(dst, src) \
    asm volatile("cp.async.cg.shared.global [%0], [%1], 16;" :: "r"(dst), "l"(src))
#define CP_COMMIT() asm volatile("cp.async.commit_group;" ::: "memory")
#define CP_WAIT0()  asm volatile("cp.async.wait_group 0;" ::: "memory")

#define PITCH  80
#define PLA_L  (128*PITCH)
#define STG_L  (3*PLA_L)          // 30720 per stage
#define SMEMB  (2*STG_L)          // 61440 -> 2 CTAs/SM

// ------------------ generic GEMM: C = scale*(A @ B^T) + bias --------------------
// emode 0: std (Cf fp32 and/or Csh/Csl split planes, cO/cI z-scatter)
// emode 1: q-up — rope cols >= 2048, split-store to Csh/Csl, ldc=NQ
// emode 2: kv-up — cols<2048: fp16 into Csh (ld 2048); cols>=2048: fp32 into Cf (ld 2048)
__global__ void __launch_bounds__(256, 2) k_gemm(
    const uint16_t* __restrict__ Ah, const uint16_t* __restrict__ Al, int lda, long long aB,
    const uint16_t* __restrict__ Bh, int ldb, long long bB,
    float* Cf, uint16_t* Csh, uint16_t* Csl, int ldc, long long cO, long long cI,
    const float* __restrict__ bias, float scale, int K, int emode)
{
    extern __shared__ __align__(16) char smem[];
    const uint32_t sb = smem_u32(smem);
    const int tid = threadIdx.x, lane = tid & 31, wid = tid >> 5;
    const int wm = wid >> 1, wn = wid & 1;     // 4m x 2n
    const int z = blockIdx.z, bm = blockIdx.y, bn = blockIdx.x;

    const uint16_t* pb0 = Ah + (size_t)z * aB + (size_t)bm * 128 * lda;
    const uint16_t* pb1 = Al + (size_t)z * aB + (size_t)bm * 128 * lda;
    const uint16_t* pb2 = Bh + (size_t)z * bB + (size_t)bn * 128 * ldb;
    const int nCh = K / 32;

    auto issue = [&](int c) {
        if (c < nCh) {
            const int kc = c * 32;
            const uint32_t sdst = sb + (c & 1) * STG_L;
            const int row = (tid >> 2);
            const int col16 = (tid & 3);
            #pragma unroll
            for (int p = 0; p < 6; p++) {
                const int pl = p >> 1;
                const int r = (p & 1) * 64 + row;
                const uint16_t* src = (pl == 0 ? pb0 : pl == 1 ? pb1 : pb2);
                const int ld = (pl < 2) ? lda : ldb;
                CP16(sdst + pl * PLA_L + r * PITCH + col16 * 16,
                     src + (size_t)r * ld + kc + col16 * 8);
            }
            CP_COMMIT();
        }
    };

    float acc[2][8][4];
    #pragma unroll
    for (int i = 0; i < 2; i++)
        #pragma unroll
        for (int j = 0; j < 8; j++)
            #pragma unroll
            for (int r = 0; r < 4; r++) acc[i][j][r] = 0.f;

    issue(0);

    for (int c = 0; c < nCh; c++) {
        CP_WAIT0();
        __syncthreads();
        issue(c + 1);

        const uint32_t sbuf = sb + (c & 1) * STG_L;
        #pragma unroll
        for (int k16 = 0; k16 < 2; k16++) {
            uint32_t af[2][2][4];
            uint32_t abase = sbuf + (wm * 32 + (lane & 15)) * PITCH
                           + (k16 * 16 + (lane >> 4) * 8) * 2;
            #pragma unroll
            for (int mt = 0; mt < 2; mt++) {
                ldm4(af[0][mt], abase + mt * 16 * PITCH);
                ldm4(af[1][mt], abase + PLA_L + mt * 16 * PITCH);
            }
            uint32_t bbase = sbuf + 2 * PLA_L
                + (wn * 64 + (lane & 7) + ((lane >> 4) << 3)) * PITCH
                + (k16 * 16 + ((lane >> 3) & 1) * 8) * 2;
            #pragma unroll
            for (int nb = 0; nb < 4; nb++) {
                uint32_t bh[4];
                ldm4(bh, bbase + nb * 16 * PITCH);
                #pragma unroll
                for (int hf = 0; hf < 2; hf++) {
                    const int nt = nb * 2 + hf;
                    #pragma unroll
                    for (int mt = 0; mt < 2; mt++) {
                        mma16816(acc[mt][nt], af[0][mt], &bh[2 * hf]);
                        mma16816(acc[mt][nt], af[1][mt], &bh[2 * hf]);
                    }
                }
            }
        }
    }

    const long long coff = (long long)(z >> 4) * cO + (long long)(z & 15) * cI;
    #pragma unroll
    for (int nt = 0; nt < 8; nt++) {
        const int gc = bn * 128 + wn * 64 + nt * 8 + (lane & 3) * 2;
        float2 bv = make_float2(0.f, 0.f);
        if (bias) bv = *(const float2*)(bias + gc);
        #pragma unroll
        for (int mt = 0; mt < 2; mt++) {
            const int r0 = bm * 128 + wm * 32 + mt * 16 + (lane >> 2);
            #pragma unroll
            for (int half = 0; half < 2; half++) {
                const int grow = r0 + half * 8;
                float v0 = acc[mt][nt][2 * half + 0] * scale + bv.x;
                float v1 = acc[mt][nt][2 * half + 1] * scale + bv.y;
                if (emode == 0) {
                    const long long gp = coff + (long long)grow * ldc + gc;
                    if (Cf) *(float2*)(Cf + gp) = make_float2(v0, v1);
                    if (Csh) {
                        uint2 s = split2(v0, v1);
                        *(uint32_t*)(Csh + gp) = s.x;
                        *(uint32_t*)(Csl + gp) = s.y;
                    }
                } else if (emode == 1) {
                    if (gc >= 2048) {
                        const int s = grow & (SSx - 1);
                        const int i2 = (gc - 2048) & (RRx - 1);
                        const int ii = s * 256 + (i2 >> 1);
                        float sn = g_sin[ii], cs = g_cos[ii];
                        float o0 = v0 * cs - v1 * sn;
                        float o1 = v1 * cs + v0 * sn;
                        v0 = o0; v1 = o1;
                    }
                    const long long gp = (long long)grow * ldc + gc;
                    uint2 s = split2(v0, v1);
                    *(uint32_t*)(Csh + gp) = s.x;
                    *(uint32_t*)(Csl + gp) = s.y;
                } else {   // emode == 2
                    if (gc < 2048)
                        *(uint32_t*)(Csh + (long long)grow * 2048 + gc) = h2pack(v0, v1);
                    else
                        *(float2*)(Cf + (long long)grow * 2048 + gc - 2048) =
                            make_float2(v0, v1);
                }
            }
        }
    }
}

// ------------------ scores GEMM with piecewise q/k addressing -------------------
// per z=(b,h): S[s,t] = sum_d q[s,d]*k[t,d] over 640 dims (128 content + 512 rope)
__global__ void __launch_bounds__(256, 2) k_gemm_qk()
{
    extern __shared__ __align__(16) char smem[];
    const uint32_t sb = smem_u32(smem);
    const int tid = threadIdx.x, lane = tid & 31, wid = tid >> 5;
    const int wm = wid >> 1, wn = wid & 1;
    const int z = blockIdx.z, bm = blockIdx.y, bn = blockIdx.x;
    const int b = z >> 4, h = z & 15;
    const long long gRow0 = (long long)b * SSx + bm * 128;   // q tokens
    const long long kRow0 = (long long)b * SSx + bn * 128;   // k tokens
    const int nCh = QKD / 32;    // 20

    auto issue = [&](int c) {
        if (c < nCh) {
            const uint32_t sdst = sb + (c & 1) * STG_L;
            const int row = (tid >> 2);
            const int col16 = (tid & 3);
            const int colA = (c < 4) ? (h * VHDx + c * 32)
                                     : (2048 + h * RRx + (c - 4) * 32);
            #pragma unroll
            for (int p = 0; p < 6; p++) {
                const int pl = p >> 1;
                const int r = (p & 1) * 64 + row;
                uint32_t dst = sdst + pl * PLA_L + r * PITCH + col16 * 16;
                if (pl == 0) {
                    CP16(dst, g_quh + (gRow0 + r) * NQ + colA + col16 * 8);
                } else if (pl == 1) {
                    CP16(dst, g_qul + (gRow0 + r) * NQ + colA + col16 * 8);
                } else {
                    if (c < 4)
                        CP16(dst, g_kch + (kRow0 + r) * UPx + h * VHDx + c * 32 + col16 * 8);
                    else
                        CP16(dst, g_krh + (kRow0 + r) * RRx + (c - 4) * 32 + col16 * 8);
                }
            }
            CP_COMMIT();
        }
    };

    float acc[2][8][4];
    #pragma unroll
    for (int i = 0; i < 2; i++)
        #pragma unroll
        for (int j = 0; j < 8; j++)
            #pragma unroll
            for (int r = 0; r < 4; r++) acc[i][j][r] = 0.f;

    issue(0);

    for (int c = 0; c < nCh; c++) {
        CP_WAIT0();
        __syncthreads();
        issue(c + 1);

        const uint32_t sbuf = sb + (c & 1) * STG_L;
        #pragma unroll
        for (int k16 = 0; k16 < 2; k16++) {
            uint32_t af[2][2][4];
            uint32_t abase = sbuf + (wm * 32 + (lane & 15)) * PITCH
                           + (k16 * 16 + (lane >> 4) * 8) * 2;
            #pragma unroll
            for (int mt = 0; mt < 2; mt++) {
                ldm4(af[0][mt], abase + mt * 16 * PITCH);
                ldm4(af[1][mt], abase + PLA_L + mt * 16 * PITCH);
            }
            uint32_t bbase = sbuf + 2 * PLA_L
                + (wn * 64 + (lane & 7) + ((lane >> 4) << 3)) * PITCH
                + (k16 * 16 + ((lane >> 3) & 1) * 8) * 2;
            #pragma unroll
            for (int nb = 0; nb < 4; nb++) {
                uint32_t bh[4];
                ldm4(bh, bbase + nb * 16 * PITCH);
                #pragma unroll
                for (int hf = 0; hf < 2; hf++) {
                    const int nt = nb * 2 + hf;
                    #pragma unroll
                    for (int mt = 0; mt < 2; mt++) {
                        mma16816(acc[mt][nt], af[0][mt], &bh[2 * hf]);
                        mma16816(acc[mt][nt], af[1][mt], &bh[2 * hf]);
                    }
                }
            }
        }
    }

    float* C = g_sc + (size_t)z * SSx * SSx;
    #pragma unroll
    for (int nt = 0; nt < 8; nt++) {
        const int gc = bn * 128 + wn * 64 + nt * 8 + (lane & 3) * 2;
        #pragma unroll
        for (int mt = 0; mt < 2; mt++) {
            const int r0 = bm * 128 + wm * 32 + mt * 16 + (lane >> 2);
            #pragma unroll
            for (int half = 0; half < 2; half++) {
                const long long gp = (long long)(r0 + half * 8) * SSx + gc;
                *(float2*)(C + gp) = make_float2(
                    acc[mt][nt][2 * half + 0] * INV_SCALE,
                    acc[mt][nt][2 * half + 1] * INV_SCALE);
            }
        }
    }
}

__global__ void k_split_x(const float* __restrict__ s, uint16_t* __restrict__ dh,
                          uint16_t* __restrict__ dl, int n2) {
    int i = blockIdx.x * 256 + threadIdx.x;
    if (i < n2) {
        float2 v = *(const float2*)(s + 2 * i);
        uint2 sp = split2(v.x, v.y);
        *(uint32_t*)(dh + 2 * i) = sp.x;
        *(uint32_t*)(dl + 2 * i) = sp.y;
    }
}
__global__ void k_trsp(const float* __restrict__ W, uint16_t* __restrict__ Wth,
                       int Kd, int Nd) {
    __shared__ float t[32][33];
    int n0 = blockIdx.x * 32, k0 = blockIdx.y * 32;
    int tx = threadIdx.x, ty = threadIdx.y;
    #pragma unroll
    for (int i = 0; i < 32; i += 8)
        t[ty + i][tx] = W[(size_t)(k0 + ty + i) * Nd + n0 + tx];
    __syncthreads();
    #pragma unroll
    for (int i = 0; i < 32; i += 8)
        Wth[(size_t)(n0 + ty + i) * Kd + k0 + tx] =
            __half_as_ushort(__float2half_rn(t[tx][ty + i]));
}
__global__ void k_cat3(float* dst, const float* a, const float* b, const float* c,
                       int na, int nb, int nc) {
    int i = blockIdx.x * 256 + threadIdx.x;
    if (i < na) dst[i] = a[i];
    else if (i < na + nb) dst[i] = b[i - na];
    else if (i < na + nb + nc) dst[i] = c[i - na - nb];
}
__global__ void k_cat2(float* dst, const float* a, const float* b, int na, int nb) {
    int i = blockIdx.x * 256 + threadIdx.x;
    if (i < na) dst[i] = a[i];
    else if (i < na + nb) dst[i] = b[i - na];
}
__global__ void k_table() {
    int idx = blockIdx.x * 256 + threadIdx.x;
    int s = idx >> 8, i = idx & 255;
    float dv = expf((float)(2 * i) * (-9.210340371976184f / (float)RRx));
    float sn, cs; sincosf((float)s * dv, &sn, &cs);
    g_sin[idx] = sn; g_cos[idx] = cs;
}
__global__ void k_rope_k() {
    int idx = blockIdx.x * 256 + threadIdx.x;
    int i = idx & 255, row = idx >> 8, s = row & (SSx - 1);
    size_t o = (size_t)row * NDOWN + 1024 + 2 * i;
    float vx = join1(g_d0sh[o],     g_d0sl[o]);
    float vy = join1(g_d0sh[o + 1], g_d0sl[o + 1]);
    float sn = g_sin[s * 256 + i], cs = g_cos[s * 256 + i];
    *(uint32_t*)(g_krh + (size_t)row * RRx + 2 * i) =
        h2pack(vx * cs - vy * sn, vy * cs + vx * sn);
}
__global__ void k_vt() {       // V [s, h*128+d] fp32 -> [z][d][s] fp16
    __shared__ float t[32][33];
    int z = blockIdx.z, b = z >> 4, h = z & 15;
    int s0 = blockIdx.x * 32, d0 = blockIdx.y * 32;
    int tx = threadIdx.x, ty = threadIdx.y;
    #pragma unroll
    for (int i = 0; i < 32; i += 8)
        t[ty + i][tx] = g_vf[(size_t)(b * SSx + s0 + ty + i) * UPx + h * VHDx + d0 + tx];
    __syncthreads();
    #pragma unroll
    for (int i = 0; i < 32; i += 8)
        g_vtsh[(size_t)z * (VHDx * SSx) + (size_t)(d0 + ty + i) * SSx + s0 + tx] =
            __half_as_ushort(__float2half_rn(t[tx][ty + i]));
}
__global__ void __launch_bounds__(128) k_softmax() {
    size_t row = blockIdx.x;
    const float* p = g_sc + row * SSx;
    int t = threadIdx.x;
    float4 v = ((const float4*)p)[t];
    float m = fmaxf(fmaxf(v.x, v.y), fmaxf(v.z, v.w));
    #pragma unroll
    for (int o = 16; o; o >>= 1) m = fmaxf(m, __shfl_xor_sync(0xffffffffu, m, o));
    __shared__ float rm[4], rs[4];
    if ((t & 31) == 0) rm[t >> 5] = m;
    __syncthreads();
    m = fmaxf(fmaxf(rm[0], rm[1]), fmaxf(rm[2], rm[3]));
    v.x = __expf(v.x - m); v.y = __expf(v.y - m);
    v.z = __expf(v.z - m); v.w = __expf(v.w - m);
    float s = v.x + v.y + v.z + v.w;
    #pragma unroll
    for (int o = 16; o; o >>= 1) s += __shfl_xor_sync(0xffffffffu, s, o);
    if ((t & 31) == 0) rs[t >> 5] = s;
    __syncthreads();
    s = rs[0] + rs[1] + rs[2] + rs[3];
    float inv = 1.f / s;
    uint2 s01 = split2(v.x * inv, v.y * inv);
    uint2 s23 = split2(v.z * inv, v.w * inv);
    *(uint2*)(g_psh + row * SSx + t * 4) = make_uint2(s01.x, s23.x);
    *(uint2*)(g_psl + row * SSx + t * 4) = make_uint2(s01.y, s23.y);
}

extern "C" void kernel_launch(void* const* d_in, const int* in_sizes, int n_in,
                              void* d_out, int out_size)
{
    const float* X    = (const float*)d_in[0];
    const float* Wdq  = (const float*)d_in[1];
    const float* bdq  = (const float*)d_in[2];
    const float* Wdkv = (const float*)d_in[3];
    const float* bdkv = (const float*)d_in[4];
    const float* Wuq  = (const float*)d_in[5];
    const float* buq  = (const float*)d_in[6];
    const float* Wuk  = (const float*)d_in[7];
    const float* buk  = (const float*)d_in[8];
    const float* Wuv  = (const float*)d_in[9];
    const float* buv  = (const float*)d_in[10];
    const float* Wqr  = (const float*)d_in[11];
    const float* bqr  = (const float*)d_in[12];
    const float* Wkr  = (const float*)d_in[13];
    const float* bkr  = (const float*)d_in[14];
    const float* Wfc  = (const float*)d_in[15];
    const float* bfc  = (const float*)d_in[16];
    float* out = (float*)d_out;

    cudaFuncSetAttribute(k_gemm, cudaFuncAttributeMaxDynamicSharedMemorySize, SMEMB);
    cudaFuncSetAttribute(k_gemm_qk, cudaFuncAttributeMaxDynamicSharedMemorySize, SMEMB);

    #define SYM(v, g) void* v; cudaGetSymbolAddress(&v, g)
    SYM(p_xsh, g_xsh);   SYM(p_xsl, g_xsl);
    SYM(p_wdth, g_wdth); SYM(p_bd, g_bd);
    SYM(p_wqth, g_wqth); SYM(p_wkvth, g_wkvth);
    SYM(p_bq, g_bq); SYM(p_bkv, g_bkv);
    SYM(p_wfcth, g_wfcth);
    SYM(p_d0sh, g_d0sh); SYM(p_d0sl, g_d0sl);
    SYM(p_quh, g_quh); SYM(p_qul, g_qul);
    SYM(p_kch, g_kch); SYM(p_vf, g_vf);
    SYM(p_sc, g_sc); SYM(p_psh, g_psh); SYM(p_psl, g_psl);
    SYM(p_vtsh, g_vtsh);
    SYM(p_ofsh, g_ofsh); SYM(p_ofsl, g_ofsl);
    #undef SYM

    dim3 tb(32, 8);
    k_table<<<SSx, 256>>>();
    k_split_x<<<(MROWS * DDx / 2) / 256, 256>>>(X, (uint16_t*)p_xsh, (uint16_t*)p_xsl,
                                                MROWS * DDx / 2);
    k_trsp<<<dim3(16, 64), tb>>>(Wdq,  (uint16_t*)p_wdth, 2048, 512);
    k_trsp<<<dim3(16, 64), tb>>>(Wdkv, (uint16_t*)p_wdth + (size_t)512 * 2048, 2048, 512);
    k_trsp<<<dim3(16, 64), tb>>>(Wkr,  (uint16_t*)p_wdth + (size_t)1024 * 2048, 2048, 512);
    k_trsp<<<dim3(64, 16), tb>>>(Wuq, (uint16_t*)p_wqth, 512, 2048);
    k_trsp<<<dim3(256, 16), tb>>>(Wqr, (uint16_t*)p_wqth + (size_t)UPx * 512, 512, 8192);
    k_trsp<<<dim3(64, 16), tb>>>(Wuk, (uint16_t*)p_wkvth, 512, 2048);
    k_trsp<<<dim3(64, 16), tb>>>(Wuv, (uint16_t*)p_wkvth + (size_t)UPx * 512, 512, 2048);
    k_trsp<<<dim3(64, 64), tb>>>(Wfc, (uint16_t*)p_wfcth, 2048, 2048);
    k_cat3<<<(NDOWN + 255) / 256, 256>>>((float*)p_bd, bdq, bdkv, bkr, 512, 512, 512);
    k_cat2<<<(NQ + 255) / 256, 256>>>((float*)p_bq, buq, bqr, UPx, RRx * HHx);
    k_cat2<<<(NKV + 255) / 256, 256>>>((float*)p_bkv, buk, buv, UPx, UPx);

    // fused down-proj: M=4096, N=1536, K=2048 (split output)
    k_gemm<<<dim3(12, 32, 1), 256, SMEMB>>>(
        (uint16_t*)p_xsh, (uint16_t*)p_xsl, DDx, 0,
        (uint16_t*)p_wdth, DDx, 0,
        nullptr, (uint16_t*)p_d0sh, (uint16_t*)p_d0sl, NDOWN, 0, 0,
        (float*)p_bd, 1.f, DDx, 0);

    // merged q-side up-proj with fused rope+split: M=4096, N=10240, K=512
    k_gemm<<<dim3(80, 32, 1), 256, SMEMB>>>(
        (uint16_t*)p_d0sh, (uint16_t*)p_d0sl, NDOWN, 0,
        (uint16_t*)p_wqth, DWN, 0,
        nullptr, (uint16_t*)p_quh, (uint16_t*)p_qul, NQ, 0, 0,
        (float*)p_bq, 1.f, DWN, 1);
    // merged kv-side up-proj: K content fp16 + V fp32: M=4096, N=4096, K=512
    k_gemm<<<dim3(32, 32, 1), 256, SMEMB>>>(
        (uint16_t*)p_d0sh + 512, (uint16_t*)p_d0sl + 512, NDOWN, 0,
        (uint16_t*)p_wkvth, DWN, 0,
        (float*)p_vf, (uint16_t*)p_kch, nullptr, 2048, 0, 0,
        (float*)p_bkv, 1.f, DWN, 2);

    k_rope_k<<<MROWS, 256>>>();
    k_vt<<<dim3(16, 4, ZBx), tb>>>();

    // scores: per z M=512, N=512, K=640, piecewise q/k sources
    k_gemm_qk<<<dim3(4, 4, ZBx), 256, SMEMB>>>();

    k_softmax<<<ZBx * SSx, 128>>>();

    // PV: per z M=512, N=128, K=512 -> split store scattered to [b,s,h*128+d]
    k_gemm<<<dim3(1, 4, ZBx), 256, SMEMB>>>(
        (uint16_t*)p_psh, (uint16_t*)p_psl, SSx, (long long)SSx * SSx,
        (uint16_t*)p_vtsh, SSx, (long long)VHDx * SSx,
        nullptr, (uint16_t*)p_ofsh, (uint16_t*)p_ofsl, UPx,
        (long long)SSx * UPx, (long long)VHDx,
        nullptr, 1.f, SSx, 0);

    // final: M=4096, N=2048, K=2048 -> out fp32
    k_gemm<<<dim3(16, 32, 1), 256, SMEMB>>>(
        (uint16_t*)p_ofsh, (uint16_t*)p_ofsl, UPx, 0,
        (uint16_t*)p_wfcth, DDx, 0,
        out, nullptr, nullptr, DDx, 0, 0, bfc, 1.f, DDx, 0);
}